// round 14
// baseline (speedup 1.0000x reference)
#include <cuda_runtime.h>
#include <cuda_bf16.h>
#include <math.h>
#include <stdint.h>

#define Bc 4
#define Sc 1024
#define Dc 1024
#define NHc 16
#define DHc 64
#define FFc 4096
#define NEc 8
#define Tc (Bc*Sc)
#define BHc (Bc*NHc)

typedef __nv_bfloat16 bf16;
typedef __nv_bfloat162 bf162;

// ---------------- fp32 scratch ----------------
__device__ float g_qkv[(size_t)Tc*3*Dc];
__device__ float g_r[Sc*Dc];
__device__ float g_ao[(size_t)Tc*Dc];
__device__ float g_ff[(size_t)Tc*Dc];
__device__ float g_h1[(size_t)Tc*Dc];
__device__ float g_h2[(size_t)Tc*Dc];
__device__ float g_h3[(size_t)Tc*Dc];
__device__ float g_moe[(size_t)Tc*Dc];
__device__ float g_gate[Tc];
__device__ int   g_cnt[NEc];
__device__ int   g_idx[NEc*Tc];

// ---------------- bf16 hi/lo scratch ----------------
__device__ bf16 g_peh[Sc*Dc],  g_pel[Sc*Dc];
__device__ bf16 g_xh[(size_t)Tc*Dc],  g_xl[(size_t)Tc*Dc];
__device__ bf16 g_quh[(size_t)Tc*Dc], g_qul[(size_t)Tc*Dc];
__device__ bf16 g_qvh[(size_t)Tc*Dc], g_qvl[(size_t)Tc*Dc];
__device__ bf16 g_kh[(size_t)Tc*Dc],  g_kl[(size_t)Tc*Dc];
__device__ bf16 g_vth[(size_t)Tc*Dc], g_vtl[(size_t)Tc*Dc];
__device__ bf16 g_rh[NHc*Sc*DHc],     g_rl[NHc*Sc*DHc];
__device__ bf16 g_ctxh[(size_t)Tc*Dc], g_ctxl[(size_t)Tc*Dc];
__device__ bf16 g_h1h[(size_t)Tc*Dc], g_h1l[(size_t)Tc*Dc];
__device__ bf16 g_h2h[(size_t)Tc*Dc], g_h2l[(size_t)Tc*Dc];
__device__ bf16 g_h3h[(size_t)Tc*Dc], g_h3l[(size_t)Tc*Dc];
__device__ bf16 g_ffhh[(size_t)Tc*FFc], g_ffhl[(size_t)Tc*FFc];

// transposed split-bf16 weights: [N,K] layout, hi + lo
#define OFF_QKV  0
#define OFF_WR   3145728
#define OFF_WO   4194304
#define OFF_FF1  5242880
#define OFF_FF2  9437184
#define OFF_WE1  13631488
#define OFF_WE2  47185920
#define OFF_WOUT 80740352
#define WTOT     81788928
__device__ bf16 g_whi[WTOT];
__device__ bf16 g_wlo[WTOT];

// ---------------- helpers ----------------
__device__ __forceinline__ uint32_t smem_u32(const void* p) {
    uint32_t a;
    asm("{ .reg .u64 t; cvta.to.shared.u64 t, %1; cvt.u32.u64 %0, t; }" : "=r"(a) : "l"(p));
    return a;
}
__device__ __forceinline__ void ldm4(uint32_t* r, uint32_t a) {
    asm volatile("ldmatrix.sync.aligned.m8n8.x4.shared.b16 {%0,%1,%2,%3}, [%4];"
        : "=r"(r[0]), "=r"(r[1]), "=r"(r[2]), "=r"(r[3]) : "r"(a));
}
__device__ __forceinline__ void mma_bf16(float* c, const uint32_t* a, uint32_t b0, uint32_t b1) {
    asm volatile("mma.sync.aligned.m16n8k16.row.col.f32.bf16.bf16.f32 "
        "{%0,%1,%2,%3}, {%4,%5,%6,%7}, {%8,%9}, {%0,%1,%2,%3};"
        : "+f"(c[0]), "+f"(c[1]), "+f"(c[2]), "+f"(c[3])
        : "r"(a[0]), "r"(a[1]), "r"(a[2]), "r"(a[3]), "r"(b0), "r"(b1));
}
__device__ __forceinline__ void split1(float v, bf16& h, bf16& l) {
    h = __float2bfloat16_rn(v);
    l = __float2bfloat16_rn(v - __bfloat162float(h));
}
__device__ __forceinline__ void split2(float x, float y, bf162& h, bf162& l) {
    h = __floats2bfloat162_rn(x, y);
    float2 hf = __bfloat1622float2(h);
    l = __floats2bfloat162_rn(x - hf.x, y - hf.y);
}
#define CPA16(dst, src, sz) \
    asm volatile("cp.async.cg.shared.global [%0], [%1], 16, %2;" :: "r"(dst), "l"(src), "r"(sz))
#define CPC()  asm volatile("cp.async.commit_group;" ::: "memory")
#define CPW1() asm volatile("cp.async.wait_group 1;" ::: "memory")
#define CPW0() asm volatile("cp.async.wait_group 0;" ::: "memory")

// ---------------- weight transpose + split: W[K,N] -> hi/lo [N,K] ----------------
__global__ __launch_bounds__(256)
void wconv(const float* __restrict__ W, bf16* __restrict__ hi,
           bf16* __restrict__ lo, int K, int N)
{
    __shared__ float t[64][68];
    int tid = threadIdx.x;
    int nb = blockIdx.x * 64, kb = blockIdx.y * 64;
    size_t eoff = (size_t)blockIdx.z * K * N;

    int j  = tid & 63;
    int r0 = tid >> 6;
    #pragma unroll
    for (int l = 0; l < 16; l++) {
        int i = r0 + l * 4;
        t[j][i] = W[eoff + (size_t)(kb + i) * N + nb + j];
    }
    __syncthreads();

    int kseg = tid & 15;
    int n0t  = tid >> 4;
    #pragma unroll
    for (int l = 0; l < 4; l++) {
        int n = n0t + l * 16;
        float4 v = *(float4*)&t[n][kseg * 4];
        bf162 h0, l0, h1, l1;
        split2(v.x, v.y, h0, l0);
        split2(v.z, v.w, h1, l1);
        size_t dst = eoff + (size_t)(nb + n) * K + kb + kseg * 4;
        *(uint2*)(hi + dst) = make_uint2(*(uint32_t*)&h0, *(uint32_t*)&h1);
        *(uint2*)(lo + dst) = make_uint2(*(uint32_t*)&l0, *(uint32_t*)&l1);
    }
}

// ---------------- elementwise fp32 -> bf16 hi/lo ----------------
__global__ __launch_bounds__(256)
void econv(const float* __restrict__ src, bf16* __restrict__ hi, bf16* __restrict__ lo)
{
    size_t i = (size_t)blockIdx.x * 1024 + threadIdx.x;
    #pragma unroll
    for (int l = 0; l < 4; l++) {
        float v = src[i + l*256];
        bf16 h, lo_;
        split1(v, h, lo_);
        hi[i + l*256] = h; lo[i + l*256] = lo_;
    }
}

// ---------------- positional embedding (bf16 hi/lo) ----------------
__global__ void pe_kernel(bf16* __restrict__ peh, bf16* __restrict__ pel) {
    int i = blockIdx.x;
    float pos = (float)(Sc - 1 - i);
    #pragma unroll
    for (int l = 0; l < 4; l++) {
        int c = threadIdx.x + l * 256;
        int j = (c < Dc/2) ? c : (c - Dc/2);
        float invf = expf(-logf(10000.f) * ((float)(2*j) / (float)Dc));
        float a = pos * invf;
        float v = (c < Dc/2) ? sinf(a) : cosf(a);
        bf16 h, lo; split1(v, h, lo);
        peh[(size_t)i*Dc + c] = h; pel[(size_t)i*Dc + c] = lo;
    }
}

// ---------------- attention operand prep (q-side pre-scaled by 0.125) ----------------
__global__ __launch_bounds__(256)
void qprep(const float* __restrict__ qkv, const float* __restrict__ ub, const float* __restrict__ vb,
           bf16* quh, bf16* qul, bf16* qvh, bf16* qvl, bf16* kh, bf16* kl)
{
    int tok = blockIdx.x;
    int b = tok >> 10, s = tok & 1023;
    #pragma unroll
    for (int l = 0; l < 4; l++) {
        int c = threadIdx.x + l*256;
        int h = c >> 6, d = c & 63;
        size_t src = (size_t)tok*3072 + c;
        float qf = qkv[src], kf = qkv[src + 1024];
        size_t dst = ((size_t)(b*NHc + h)*Sc + s)*64 + d;
        bf16 hh, ll;
        split1((qf + ub[c]) * 0.125f, hh, ll); quh[dst] = hh; qul[dst] = ll;
        split1((qf + vb[c]) * 0.125f, hh, ll); qvh[dst] = hh; qvl[dst] = ll;
        split1(kf, hh, ll);                   kh[dst] = hh;  kl[dst] = ll;
    }
}
__global__ __launch_bounds__(256)
void vtprep(const float* __restrict__ qkv, bf16* vth, bf16* vtl)
{
    __shared__ float t[32][33];
    int tx = threadIdx.x & 31, ty = threadIdx.x >> 5;
    int s0 = blockIdx.x * 32, d0 = blockIdx.y * 32, bh = blockIdx.z;
    int b = bh >> 4, h = bh & 15;
    #pragma unroll
    for (int j = 0; j < 4; j++) {
        int sl = ty + j*8;
        t[sl][tx] = qkv[((size_t)(b*Sc + s0 + sl))*3072 + 2048 + h*64 + d0 + tx];
    }
    __syncthreads();
    #pragma unroll
    for (int j = 0; j < 4; j++) {
        int dl = ty + j*8;
        float v = t[tx][dl];
        bf16 hh, ll; split1(v, hh, ll);
        size_t dst = ((size_t)bh*64 + d0 + dl)*Sc + s0 + tx;
        vth[dst] = hh; vtl[dst] = ll;
    }
}
__global__ __launch_bounds__(256)
void rprep(const float* __restrict__ r, bf16* rh, bf16* rl)
{
    int s = blockIdx.x;
    #pragma unroll
    for (int l = 0; l < 4; l++) {
        int c = threadIdx.x + l*256;
        int h = c >> 6, d = c & 63;
        float v = r[(size_t)s*Dc + c];
        bf16 hh, ll; split1(v, hh, ll);
        size_t dst = ((size_t)h*Sc + s)*64 + d;
        rh[dst] = hh; rl[dst] = ll;
    }
}

// ---------------- HMMA split-bf16 GEMM: CTA 128x256, warp tile 64x64 ----------------
// smem per stage: AH(10240) AL(10240) BH(20480) BL(20480) = 61440; 2 stages.
#define STG_BYTES 61440
#define TG_SMEM   (2*STG_BYTES)

template<int EPI, int OBF>
__global__ __launch_bounds__(256, 1)
void tgemm(const bf16* __restrict__ Ahi, const bf16* __restrict__ Alo,
           const bf16* __restrict__ Bhi, const bf16* __restrict__ Blo,
           float* __restrict__ C, bf16* __restrict__ Chi, bf16* __restrict__ Clo,
           int M, int N, int K,
           const float* __restrict__ bias, const float* __restrict__ rowScale,
           const int* __restrict__ gatherBase, const int* __restrict__ cntBase,
           size_t eStrideB, int eStrideBias)
{
    extern __shared__ char sm[];

    int e = blockIdx.z;
    const int* gather = gatherBase ? gatherBase + e * Tc : nullptr;
    int limit = cntBase ? cntBase[e] : M;
    int m0 = blockIdx.y * 128;
    if (m0 >= limit) return;
    int n0 = blockIdx.x * 256;
    const bf16* BhiE = Bhi + (size_t)e * eStrideB;
    const bf16* BloE = Blo + (size_t)e * eStrideB;
    const float* biasE = (EPI >= 1) ? bias + (size_t)e * eStrideBias : bias;

    int tid = threadIdx.x, wid = tid >> 5, lane = tid & 31;
    int wm = (wid & 1) * 64, wn = (wid >> 1) * 64;
    uint32_t sbase = smem_u32(sm);

    // A staging: 512 lines (128 rows x 4 segs), 2/thread; B: 1024 lines, 4/thread
    const bf16 *aph[2], *apl[2], *bph[4], *bpl[4];
    uint32_t aoff[2], boff[4], asz[2];
    #pragma unroll
    for (int l = 0; l < 2; l++) {
        int slot = tid + 256*l;
        int row = slot >> 2, seg = slot & 3;
        aoff[l] = (uint32_t)(row * 80 + seg * 16);
        int gr = m0 + row;
        if (gr < limit) {
            int sr = gather ? gather[gr] : gr;
            aph[l] = Ahi + (size_t)sr * K + seg * 8;
            apl[l] = Alo + (size_t)sr * K + seg * 8;
            asz[l] = 16;
        } else {
            aph[l] = Ahi; apl[l] = Alo; asz[l] = 0;
        }
    }
    #pragma unroll
    for (int l = 0; l < 4; l++) {
        int slot = tid + 256*l;
        int row = slot >> 2, seg = slot & 3;
        boff[l] = (uint32_t)(row * 80 + seg * 16);
        size_t off = (size_t)(n0 + row) * K + seg * 8;
        bph[l] = BhiE + off; bpl[l] = BloE + off;
    }

    int t4 = lane >> 3;
    int rr = (lane & 7) + (t4 & 1) * 8;
    int cc = (t4 >> 1) * 8;

    float acc[4][8][4];
    #pragma unroll
    for (int i = 0; i < 4; i++)
        #pragma unroll
        for (int j = 0; j < 8; j++)
            #pragma unroll
            for (int q = 0; q < 4; q++) acc[i][j][q] = 0.f;

    int Kc = K >> 5;

    #pragma unroll
    for (int s = 0; s < 2; s++) {
        if (s < Kc) {
            uint32_t bb = sbase + s * STG_BYTES;
            int ko = s * 32;
            #pragma unroll
            for (int l = 0; l < 2; l++) {
                CPA16(bb + aoff[l],         aph[l] + ko, asz[l]);
                CPA16(bb + 10240 + aoff[l], apl[l] + ko, asz[l]);
            }
            #pragma unroll
            for (int l = 0; l < 4; l++) {
                CPA16(bb + 20480 + boff[l], bph[l] + ko, 16u);
                CPA16(bb + 40960 + boff[l], bpl[l] + ko, 16u);
            }
            CPC();
        }
    }

    for (int c = 0; c < Kc; c++) {
        if (c + 1 < Kc) { CPW1(); } else { CPW0(); }
        __syncthreads();

        uint32_t sb = sbase + (uint32_t)(c & 1) * STG_BYTES;
        uint32_t baAH = sb, baAL = sb + 10240;
        uint32_t baBH = sb + 20480, baBL = sb + 40960;

        #pragma unroll
        for (int k16 = 0; k16 < 32; k16 += 16) {
            uint32_t aH[4][4], aL[4][4];
            #pragma unroll
            for (int mi = 0; mi < 4; mi++) {
                uint32_t off = ((uint32_t)(wm + mi*16 + rr) * 40u + (uint32_t)(k16 + cc)) * 2u;
                ldm4(aH[mi], baAH + off);
                ldm4(aL[mi], baAL + off);
            }
            #pragma unroll
            for (int ni = 0; ni < 4; ni++) {
                uint32_t bH[4], bL[4];
                uint32_t off = ((uint32_t)(wn + ni*16 + rr) * 40u + (uint32_t)(k16 + cc)) * 2u;
                ldm4(bH, baBH + off);
                ldm4(bL, baBL + off);
                #pragma unroll
                for (int mi = 0; mi < 4; mi++)
                    #pragma unroll
                    for (int h = 0; h < 2; h++) {
                        int j = ni*2 + h;
                        mma_bf16(acc[mi][j], aH[mi], bH[h], bH[h+2]);
                        mma_bf16(acc[mi][j], aH[mi], bL[h], bL[h+2]);
                        mma_bf16(acc[mi][j], aL[mi], bH[h], bH[h+2]);
                    }
            }
        }
        __syncthreads();

        if (c + 2 < Kc) {
            uint32_t bb = sbase + (uint32_t)(c & 1) * STG_BYTES;
            int ko = (c + 2) * 32;
            #pragma unroll
            for (int l = 0; l < 2; l++) {
                CPA16(bb + aoff[l],         aph[l] + ko, asz[l]);
                CPA16(bb + 10240 + aoff[l], apl[l] + ko, asz[l]);
            }
            #pragma unroll
            for (int l = 0; l < 4; l++) {
                CPA16(bb + 20480 + boff[l], bph[l] + ko, 16u);
                CPA16(bb + 40960 + boff[l], bpl[l] + ko, 16u);
            }
            CPC();
        }
    }

    #pragma unroll
    for (int mi = 0; mi < 4; mi++) {
        #pragma unroll
        for (int half = 0; half < 2; half++) {
            int gr = m0 + wm + mi*16 + (lane >> 2) + half*8;
            if (gr >= limit) continue;
            int crow = gather ? gather[gr] : gr;
            float rs = 1.f;
            if (EPI == 3) rs = rowScale[crow];
            #pragma unroll
            for (int j = 0; j < 8; j++) {
                int col = n0 + wn + j*8 + (lane & 3)*2;
                float vx = acc[mi][j][half*2 + 0];
                float vy = acc[mi][j][half*2 + 1];
                if (EPI >= 1) { vx += biasE[col]; vy += biasE[col+1]; }
                if (EPI == 2) { vx = fmaxf(vx, 0.f); vy = fmaxf(vy, 0.f); }
                if (EPI == 3) { vx *= rs; vy *= rs; }
                if (OBF == 0) {
                    *(float2*)(C + (size_t)crow * N + col) = make_float2(vx, vy);
                } else {
                    bf162 h, l; split2(vx, vy, h, l);
                    *(bf162*)(Chi + (size_t)crow * N + col) = h;
                    *(bf162*)(Clo + (size_t)crow * N + col) = l;
                }
            }
        }
    }
}

// ---------------- fused TXL attention ----------------
#define FA_QUH 0
#define FA_QUL 9216
#define FA_QVH 18432
#define FA_QVL 27648
#define FA_KH  36864
#define FA_KL  46080
#define FA_RH  55296
#define FA_RL  73728
#define FA_VH  92160
#define FA_VL  101376
#define FA_PH  110592
#define FA_PL  119808
#define FA_BD  129024
#define FA_RED (FA_BD + 33792)
#define FA_SMEM (FA_RED + 1024)

__global__ __launch_bounds__(256, 1)
void fattn(const bf16* __restrict__ quh, const bf16* __restrict__ qul,
           const bf16* __restrict__ qvh, const bf16* __restrict__ qvl,
           const bf16* __restrict__ kh,  const bf16* __restrict__ kl,
           const bf16* __restrict__ rhp, const bf16* __restrict__ rlp,
           const bf16* __restrict__ vth, const bf16* __restrict__ vtl,
           bf16* __restrict__ ctxh, bf16* __restrict__ ctxl)
{
    extern __shared__ char sm[];
    int qt = 15 - blockIdx.x;
    int bh = blockIdx.y;
    int b = bh >> 4, h = bh & 15;
    int q0 = qt * 64;
    uint32_t sb = smem_u32(sm);
    int tid = threadIdx.x, wid = tid >> 5, lane = tid & 31;
    int wm = (wid & 3) * 16, wn = (wid >> 2) * 32;
    int wcol = wid >> 2;
    int t4l = lane >> 3;
    int rr = (lane & 7) + (t4l & 1) * 8;
    int cc = (t4l >> 1) * 8;
    int qrow = (lane >> 2);
    int kc0 = (lane & 3) * 2;

    #pragma unroll
    for (int i = 0; i < 2; i++) {
        int slot = tid + 256*i;
        int row = slot >> 3, seg = slot & 7;
        size_t g = ((size_t)bh*Sc + q0 + row)*64 + seg*8;
        *(uint4*)(sm + FA_QUH + row*144 + seg*16) = *(const uint4*)(quh + g);
        *(uint4*)(sm + FA_QUL + row*144 + seg*16) = *(const uint4*)(qul + g);
        *(uint4*)(sm + FA_QVH + row*144 + seg*16) = *(const uint4*)(qvh + g);
        *(uint4*)(sm + FA_QVL + row*144 + seg*16) = *(const uint4*)(qvl + g);
    }

    float mrow[2] = {-1e30f, -1e30f}, lrow[2] = {0.f, 0.f};
    float oacc[4][4];
    #pragma unroll
    for (int j = 0; j < 4; j++)
        #pragma unroll
        for (int q = 0; q < 4; q++) oacc[j][q] = 0.f;

    for (int kt = 0; kt <= qt; kt++) {
        int k0 = kt * 64;
        int t0 = kt - qt + 15;
        __syncthreads();

        #pragma unroll
        for (int i = 0; i < 2; i++) {
            int slot = tid + 256*i;
            int row = slot >> 3, seg = slot & 7;
            size_t gk = ((size_t)bh*Sc + k0 + row)*64 + seg*8;
            *(uint4*)(sm + FA_KH + row*144 + seg*16) = *(const uint4*)(kh + gk);
            *(uint4*)(sm + FA_KL + row*144 + seg*16) = *(const uint4*)(kl + gk);
            size_t gv = ((size_t)bh*64 + row)*Sc + k0 + seg*8;
            *(uint4*)(sm + FA_VH + row*144 + seg*16) = *(const uint4*)(vth + gv);
            *(uint4*)(sm + FA_VL + row*144 + seg*16) = *(const uint4*)(vtl + gv);
        }
        int tfrom = (kt == 0) ? t0 : t0 + 1;
        for (int t = tfrom; t <= t0 + 1 && t <= 15; t++) {
            int hoff = (t & 1) * 64;
            #pragma unroll
            for (int i = 0; i < 2; i++) {
                int slot = tid + 256*i;
                int row = slot >> 3, seg = slot & 7;
                size_t gr = ((size_t)h*Sc + t*64 + row)*64 + seg*8;
                *(uint4*)(sm + FA_RH + (hoff + row)*144 + seg*16) = *(const uint4*)(rhp + gr);
                *(uint4*)(sm + FA_RL + (hoff + row)*144 + seg*16) = *(const uint4*)(rlp + gr);
            }
        }
        __syncthreads();

        for (int t = tfrom; t <= t0 + 1 && t <= 15; t++) {
            int hoff = (t & 1) * 64;
            float bacc[4][4];
            #pragma unroll
            for (int j = 0; j < 4; j++)
                #pragma unroll
                for (int q = 0; q < 4; q++) bacc[j][q] = 0.f;
            #pragma unroll
            for (int k16 = 0; k16 < 64; k16 += 16) {
                uint32_t aH[4], aL[4];
                uint32_t offA = ((uint32_t)(wm + rr) * 72u + (uint32_t)(k16 + cc)) * 2u;
                ldm4(aH, sb + FA_QVH + offA);
                ldm4(aL, sb + FA_QVL + offA);
                uint32_t bH[2][4], bL[2][4];
                #pragma unroll
                for (int ni = 0; ni < 2; ni++) {
                    uint32_t offB = ((uint32_t)(hoff + wn + ni*16 + rr) * 72u + (uint32_t)(k16 + cc)) * 2u;
                    ldm4(bH[ni], sb + FA_RH + offB);
                    ldm4(bL[ni], sb + FA_RL + offB);
                }
                #pragma unroll
                for (int ni = 0; ni < 2; ni++)
                    #pragma unroll
                    for (int hb = 0; hb < 2; hb++) {
                        int j = ni*2 + hb;
                        mma_bf16(bacc[j], aH, bH[ni][hb], bH[ni][hb+2]);
                        mma_bf16(bacc[j], aH, bL[ni][hb], bL[ni][hb+2]);
                        mma_bf16(bacc[j], aL, bH[ni][hb], bH[ni][hb+2]);
                    }
            }
            #pragma unroll
            for (int half = 0; half < 2; half++) {
                int row = wm + qrow + half*8;
                #pragma unroll
                for (int j = 0; j < 4; j++) {
                    int col = hoff + wn + j*8 + kc0;
                    *(float2*)(sm + FA_BD + row*528 + col*4) =
                        make_float2(bacc[j][half*2], bacc[j][half*2+1]);
                }
            }
        }

        float s[4][4];
        #pragma unroll
        for (int j = 0; j < 4; j++)
            #pragma unroll
            for (int q = 0; q < 4; q++) s[j][q] = 0.f;
        #pragma unroll
        for (int k16 = 0; k16 < 64; k16 += 16) {
            uint32_t aH[4], aL[4];
            uint32_t offA = ((uint32_t)(wm + rr) * 72u + (uint32_t)(k16 + cc)) * 2u;
            ldm4(aH, sb + FA_QUH + offA);
            ldm4(aL, sb + FA_QUL + offA);
            uint32_t bH[2][4], bL[2][4];
            #pragma unroll
            for (int ni = 0; ni < 2; ni++) {
                uint32_t offB = ((uint32_t)(wn + ni*16 + rr) * 72u + (uint32_t)(k16 + cc)) * 2u;
                ldm4(bH[ni], sb + FA_KH + offB);
                ldm4(bL[ni], sb + FA_KL + offB);
            }
            #pragma unroll
            for (int ni = 0; ni < 2; ni++)
                #pragma unroll
                for (int hb = 0; hb < 2; hb++) {
                    int j = ni*2 + hb;
                    mma_bf16(s[j], aH, bH[ni][hb], bH[ni][hb+2]);
                    mma_bf16(s[j], aH, bL[ni][hb], bL[ni][hb+2]);
                    mma_bf16(s[j], aL, bH[ni][hb], bH[ni][hb+2]);
                }
        }
        __syncthreads();

        bool diag = (kt == qt);
        int ringbase = (t0 & 1) * 64;
        float mt2[2], sc2[2], rs2[2];

        #pragma unroll
        for (int half = 0; half < 2; half++) {
            int row = wm + qrow + half*8;
            float mt = -1e30f;
            #pragma unroll
            for (int j = 0; j < 4; j++) {
                #pragma unroll
                for (int c2 = 0; c2 < 2; c2++) {
                    int colk = wn + j*8 + kc0 + c2;
                    int jcol = colk - row + 63;
                    int phys = (ringbase + jcol) & 127;
                    float val = s[j][half*2 + c2] +
                        *(const float*)(sm + FA_BD + row*528 + phys*4);
                    if (diag && colk > row) val = -1e30f;
                    s[j][half*2 + c2] = val;
                    mt = fmaxf(mt, val);
                }
            }
            mt = fmaxf(mt, __shfl_xor_sync(0xFFFFFFFFu, mt, 1));
            mt = fmaxf(mt, __shfl_xor_sync(0xFFFFFFFFu, mt, 2));
            mt2[half] = mt;
            if ((lane & 3) == 0)
                *(float*)(sm + FA_RED + (wcol*64 + row)*4) = mt;
        }
        __syncthreads();

        #pragma unroll
        for (int half = 0; half < 2; half++) {
            int row = wm + qrow + half*8;
            float other = *(const float*)(sm + FA_RED + ((1-wcol)*64 + row)*4);
            float mnew = fmaxf(mrow[half], fmaxf(mt2[half], other));
            float scale = __expf(mrow[half] - mnew);
            sc2[half] = scale;
            float rs = 0.f;
            #pragma unroll
            for (int j = 0; j < 4; j++) {
                #pragma unroll
                for (int c2 = 0; c2 < 2; c2++) {
                    float p = __expf(s[j][half*2 + c2] - mnew);
                    s[j][half*2 + c2] = p;
                    rs += p;
                }
            }
            rs += __shfl_xor_sync(0xFFFFFFFFu, rs, 1);
            rs += __shfl_xor_sync(0xFFFFFFFFu, rs, 2);
            rs2[half] = rs;
            if ((lane & 3) == 0)
                *(float*)(sm + FA_RED + 512 + (wcol*64 + row)*4) = rs;
            mrow[half] = mnew;
            #pragma unroll
            for (int j = 0; j < 4; j++) {
                oacc[j][half*2 + 0] *= scale;
                oacc[j][half*2 + 1] *= scale;
            }
            #pragma unroll
            for (int j = 0; j < 4; j++) {
                int col = wn + j*8 + kc0;
                bf162 hh, ll;
                split2(s[j][half*2], s[j][half*2+1], hh, ll);
                *(bf162*)(sm + FA_PH + row*144 + col*2) = hh;
                *(bf162*)(sm + FA_PL + row*144 + col*2) = ll;
            }
        }
        __syncthreads();

        #pragma unroll
        for (int half = 0; half < 2; half++) {
            int row = wm + qrow + half*8;
            float other = *(const float*)(sm + FA_RED + 512 + ((1-wcol)*64 + row)*4);
            lrow[half] = lrow[half] * sc2[half] + rs2[half] + other;
        }

        #pragma unroll
        for (int k16 = 0; k16 < 64; k16 += 16) {
            uint32_t aH[4], aL[4];
            uint32_t offA = ((uint32_t)(wm + rr) * 72u + (uint32_t)(k16 + cc)) * 2u;
            ldm4(aH, sb + FA_PH + offA);
            ldm4(aL, sb + FA_PL + offA);
            uint32_t bH[2][4], bL[2][4];
            #pragma unroll
            for (int ni = 0; ni < 2; ni++) {
                uint32_t offB = ((uint32_t)(wn + ni*16 + rr) * 72u + (uint32_t)(k16 + cc)) * 2u;
                ldm4(bH[ni], sb + FA_VH + offB);
                ldm4(bL[ni], sb + FA_VL + offB);
            }
            #pragma unroll
            for (int ni = 0; ni < 2; ni++)
                #pragma unroll
                for (int hb = 0; hb < 2; hb++) {
                    int j = ni*2 + hb;
                    mma_bf16(oacc[j], aH, bH[ni][hb], bH[ni][hb+2]);
                    mma_bf16(oacc[j], aH, bL[ni][hb], bL[ni][hb+2]);
                    mma_bf16(oacc[j], aL, bH[ni][hb], bH[ni][hb+2]);
                }
        }
    }

    #pragma unroll
    for (int half = 0; half < 2; half++) {
        int row = wm + qrow + half*8;
        int tok = b*Sc + q0 + row;
        float inv = 1.f / lrow[half];
        #pragma unroll
        for (int j = 0; j < 4; j++) {
            int col = h*64 + wn + j*8 + kc0;
            bf162 hh, ll;
            split2(oacc[j][half*2] * inv, oacc[j][half*2+1] * inv, hh, ll);
            *(bf162*)(ctxh + (size_t)tok*Dc + col) = hh;
            *(bf162*)(ctxl + (size_t)tok*Dc + col) = ll;
        }
    }
}

// ---------------- residual + layernorm ----------------
template<int OBF>
__global__ __launch_bounds__(256)
void rln_k(const float* __restrict__ x, const float* __restrict__ y,
           const float* __restrict__ g, const float* __restrict__ bta,
           float* __restrict__ out, bf16* __restrict__ oh, bf16* __restrict__ ol)
{
    int row = blockIdx.x;
    int tid = threadIdx.x;
    __shared__ float red[256];
    float v[4];
    float s = 0.f, ss = 0.f;
    #pragma unroll
    for (int l = 0; l < 4; l++) {
        size_t idx = (size_t)row*Dc + tid + l*256;
        float val = x[idx] + y[idx];
        v[l] = val; s += val; ss += val*val;
    }
    red[tid] = s; __syncthreads();
    for (int st = 128; st > 0; st >>= 1) { if (tid < st) red[tid] += red[tid+st]; __syncthreads(); }
    float mean = red[0] * (1.f/Dc); __syncthreads();
    red[tid] = ss; __syncthreads();
    for (int st = 128; st > 0; st >>= 1) { if (tid < st) red[tid] += red[tid+st]; __syncthreads(); }
    float var = red[0] * (1.f/Dc) - mean*mean;
    float inv = rsqrtf(var + 1e-5f);
    #pragma unroll
    for (int l = 0; l < 4; l++) {
        int c = tid + l*256;
        float o = (v[l] - mean) * inv * g[c] + bta[c];
        out[(size_t)row*Dc + c] = o;
        if (OBF) {
            bf16 hh, ll; split1(o, hh, ll);
            oh[(size_t)row*Dc + c] = hh;
            ol[(size_t)row*Dc + c] = ll;
        }
    }
}

// ---------------- router ----------------
__global__ void zero_cnt(int* cnt) { if (threadIdx.x < NEc) cnt[threadIdx.x] = 0; }

__global__ __launch_bounds__(256)
void router_k(const float* __restrict__ h2, const float* __restrict__ Wg,
              float* __restrict__ gate, int* __restrict__ cnt, int* __restrict__ idxlist)
{
    int warp = (blockIdx.x * blockDim.x + threadIdx.x) >> 5;
    int lane = threadIdx.x & 31;
    if (warp >= Tc) return;
    const float* hrow = h2 + (size_t)warp * Dc;
    float logit[NEc];
    #pragma unroll
    for (int e = 0; e < NEc; e++) {
        float p = 0.f;
        for (int d = lane; d < Dc; d += 32) p += hrow[d] * Wg[d*NEc + e];
        #pragma unroll
        for (int off = 16; off > 0; off >>= 1) p += __shfl_xor_sync(0xFFFFFFFFu, p, off);
        logit[e] = p;
    }
    float m = logit[0]; int am = 0;
    #pragma unroll
    for (int e = 1; e < NEc; e++) if (logit[e] > m) { m = logit[e]; am = e; }
    float sum = 0.f;
    #pragma unroll
    for (int e = 0; e < NEc; e++) sum += expf(logit[e] - m);
    if (lane == 0) {
        gate[warp] = 1.f / sum;
        int pos = atomicAdd(&cnt[am], 1);
        idxlist[am*Tc + pos] = warp;
    }
}

// ---------------- launch ----------------
extern "C" void kernel_launch(void* const* d_in, const int* in_sizes, int n_in,
                              void* d_out, int out_size)
{
    const float* x    = (const float*)d_in[0];
    const float* Wqkv = (const float*)d_in[1];
    const float* Wo   = (const float*)d_in[2];
    const float* Wr   = (const float*)d_in[3];
    const float* u_b  = (const float*)d_in[4];
    const float* v_b  = (const float*)d_in[5];
    const float* ln1g = (const float*)d_in[6];
    const float* ln1b = (const float*)d_in[7];
    const float* Wff1 = (const float*)d_in[8];
    const float* bff1 = (const float*)d_in[9];
    const float* Wff2 = (const float*)d_in[10];
    const float* bff2 = (const float*)d_in[11];
    const float* ln2g = (const float*)d_in[12];
    const float* ln2b = (const float*)d_in[13];
    const float* Wg   = (const float*)d_in[14];
    const float* We1  = (const float*)d_in[15];
    const float* be1  = (const float*)d_in[16];
    const float* We2  = (const float*)d_in[17];
    const float* be2  = (const float*)d_in[18];
    const float* ln3g = (const float*)d_in[19];
    const float* ln3b = (const float*)d_in[20];
    const float* Wout = (const float*)d_in[21];
    float* out = (float*)d_out;

    static int inited = 0;
    if (!inited) {
        cudaFuncSetAttribute(tgemm<0,0>, cudaFuncAttributeMaxDynamicSharedMemorySize, TG_SMEM);
        cudaFuncSetAttribute(tgemm<1,0>, cudaFuncAttributeMaxDynamicSharedMemorySize, TG_SMEM);
        cudaFuncSetAttribute(tgemm<2,1>, cudaFuncAttributeMaxDynamicSharedMemorySize, TG_SMEM);
        cudaFuncSetAttribute(tgemm<3,0>, cudaFuncAttributeMaxDynamicSharedMemorySize, TG_SMEM);
        cudaFuncSetAttribute(fattn,      cudaFuncAttributeMaxDynamicSharedMemorySize, FA_SMEM);
        inited = 1;
    }

    float *qkv, *r, *ao, *ff, *h1, *h2, *h3, *moe, *gate;
    int *cnt, *idx;
    bf16 *whi, *wlo, *peh, *pel, *xh, *xl;
    bf16 *quh, *qul, *qvh, *qvl, *kh, *kl, *vth, *vtl, *rh, *rl;
    bf16 *ctxh, *ctxl, *h1h, *h1l, *h2h, *h2l, *h3h, *h3l, *ffhh, *ffhl;

    cudaGetSymbolAddress((void**)&qkv, g_qkv);
    cudaGetSymbolAddress((void**)&r,   g_r);
    cudaGetSymbolAddress((void**)&ao,  g_ao);
    cudaGetSymbolAddress((void**)&ff,  g_ff);
    cudaGetSymbolAddress((void**)&h1,  g_h1);
    cudaGetSymbolAddress((void**)&h2,  g_h2);
    cudaGetSymbolAddress((void**)&h3,  g_h3);
    cudaGetSymbolAddress((void**)&moe, g_moe);
    cudaGetSymbolAddress((void**)&gate,g_gate);
    cudaGetSymbolAddress((void**)&cnt, g_cnt);
    cudaGetSymbolAddress((void**)&idx, g_idx);
    cudaGetSymbolAddress((void**)&whi, g_whi);
    cudaGetSymbolAddress((void**)&wlo, g_wlo);
    cudaGetSymbolAddress((void**)&peh, g_peh);
    cudaGetSymbolAddress((void**)&pel, g_pel);
    cudaGetSymbolAddress((void**)&xh,  g_xh);
    cudaGetSymbolAddress((void**)&xl,  g_xl);
    cudaGetSymbolAddress((void**)&quh, g_quh);
    cudaGetSymbolAddress((void**)&qul, g_qul);
    cudaGetSymbolAddress((void**)&qvh, g_qvh);
    cudaGetSymbolAddress((void**)&qvl, g_qvl);
    cudaGetSymbolAddress((void**)&kh,  g_kh);
    cudaGetSymbolAddress((void**)&kl,  g_kl);
    cudaGetSymbolAddress((void**)&vth, g_vth);
    cudaGetSymbolAddress((void**)&vtl, g_vtl);
    cudaGetSymbolAddress((void**)&rh,  g_rh);
    cudaGetSymbolAddress((void**)&rl,  g_rl);
    cudaGetSymbolAddress((void**)&ctxh,g_ctxh);
    cudaGetSymbolAddress((void**)&ctxl,g_ctxl);
    cudaGetSymbolAddress((void**)&h1h, g_h1h);
    cudaGetSymbolAddress((void**)&h1l, g_h1l);
    cudaGetSymbolAddress((void**)&h2h, g_h2h);
    cudaGetSymbolAddress((void**)&h2l, g_h2l);
    cudaGetSymbolAddress((void**)&h3h, g_h3h);
    cudaGetSymbolAddress((void**)&h3l, g_h3l);
    cudaGetSymbolAddress((void**)&ffhh,g_ffhh);
    cudaGetSymbolAddress((void**)&ffhl,g_ffhl);

    // weight transpose + split
    wconv<<<dim3(3072/64, 1024/64), 256>>>(Wqkv, whi+OFF_QKV,  wlo+OFF_QKV,  1024, 3072);
    wconv<<<dim3(1024/64, 1024/64), 256>>>(Wr,   whi+OFF_WR,   wlo+OFF_WR,   1024, 1024);
    wconv<<<dim3(1024/64, 1024/64), 256>>>(Wo,   whi+OFF_WO,   wlo+OFF_WO,   1024, 1024);
    wconv<<<dim3(4096/64, 1024/64), 256>>>(Wff1, whi+OFF_FF1,  wlo+OFF_FF1,  1024, 4096);
    wconv<<<dim3(1024/64, 4096/64), 256>>>(Wff2, whi+OFF_FF2,  wlo+OFF_FF2,  4096, 1024);
    wconv<<<dim3(1024/64, 1024/64), 256>>>(Wout, whi+OFF_WOUT, wlo+OFF_WOUT, 1024, 1024);
    wconv<<<dim3(4096/64, 1024/64, NEc), 256>>>(We1, whi+OFF_WE1, wlo+OFF_WE1, 1024, 4096);
    wconv<<<dim3(1024/64, 4096/64, NEc), 256>>>(We2, whi+OFF_WE2, wlo+OFF_WE2, 4096, 1024);

    pe_kernel<<<Sc, 256>>>(peh, pel);
    econv<<<Tc, 256>>>(x, xh, xl);

    // projections
    tgemm<0,0><<<dim3(3072/256, Tc/128), 256, TG_SMEM>>>(xh, xl, whi+OFF_QKV, wlo+OFF_QKV,
        qkv, nullptr, nullptr, Tc, 3072, 1024, nullptr, nullptr, nullptr, nullptr, 0, 0);
    tgemm<0,0><<<dim3(1024/256, Sc/128), 256, TG_SMEM>>>(peh, pel, whi+OFF_WR, wlo+OFF_WR,
        r, nullptr, nullptr, Sc, 1024, 1024, nullptr, nullptr, nullptr, nullptr, 0, 0);

    // attention prep
    qprep<<<Tc, 256>>>(qkv, u_b, v_b, quh, qul, qvh, qvl, kh, kl);
    vtprep<<<dim3(Sc/32, 2, BHc), 256>>>(qkv, vth, vtl);
    rprep<<<Sc, 256>>>(r, rh, rl);

    // fused attention
    fattn<<<dim3(16, BHc), 256, FA_SMEM>>>(quh, qul, qvh, qvl, kh, kl, rh, rl,
                                           vth, vtl, ctxh, ctxl);
    tgemm<0,0><<<dim3(1024/256, Tc/128), 256, TG_SMEM>>>(ctxh, ctxl, whi+OFF_WO, wlo+OFF_WO,
        ao, nullptr, nullptr, Tc, 1024, 1024, nullptr, nullptr, nullptr, nullptr, 0, 0);
    rln_k<1><<<Tc, 256>>>(x, ao, ln1g, ln1b, h1, h1h, h1l);

    // FFN
    tgemm<2,1><<<dim3(4096/256, Tc/128), 256, TG_SMEM>>>(h1h, h1l, whi+OFF_FF1, wlo+OFF_FF1,
        nullptr, ffhh, ffhl, Tc, 4096, 1024, bff1, nullptr, nullptr, nullptr, 0, 0);
    tgemm<1,0><<<dim3(1024/256, Tc/128), 256, TG_SMEM>>>(ffhh, ffhl, whi+OFF_FF2, wlo+OFF_FF2,
        ff, nullptr, nullptr, Tc, 1024, 4096, bff2, nullptr, nullptr, nullptr, 0, 0);
    rln_k<1><<<Tc, 256>>>(h1, ff, ln2g, ln2b, h2, h2h, h2l);

    // MoE
    zero_cnt<<<1, 32>>>(cnt);
    router_k<<<Tc/8, 256>>>(h2, Wg, gate, cnt, idx);
    tgemm<2,1><<<dim3(4096/256, Tc/128, NEc), 256, TG_SMEM>>>(
        h2h, h2l, whi+OFF_WE1, wlo+OFF_WE1,
        nullptr, ffhh, ffhl, Tc, 4096, 1024, be1, nullptr, idx, cnt,
        (size_t)FFc*Dc, FFc);
    tgemm<3,0><<<dim3(1024/256, Tc/128, NEc), 256, TG_SMEM>>>(
        ffhh, ffhl, whi+OFF_WE2, wlo+OFF_WE2,
        moe, nullptr, nullptr, Tc, 1024, 4096, be2, gate, idx, cnt,
        (size_t)Dc*FFc, Dc);
    rln_k<1><<<Tc, 256>>>(h2, moe, ln3g, ln3b, h3, h3h, h3l);

    // output projection
    tgemm<0,0><<<dim3(1024/256, Tc/128), 256, TG_SMEM>>>(h3h, h3l, whi+OFF_WOUT, wlo+OFF_WOUT,
        out, nullptr, nullptr, Tc, 1024, 1024, nullptr, nullptr, nullptr, nullptr, 0, 0);
}

// round 15
// speedup vs baseline: 1.0646x; 1.0646x over previous
#include <cuda_runtime.h>
#include <cuda_bf16.h>
#include <math.h>
#include <stdint.h>

#define Bc 4
#define Sc 1024
#define Dc 1024
#define NHc 16
#define DHc 64
#define FFc 4096
#define NEc 8
#define Tc (Bc*Sc)
#define BHc (Bc*NHc)

typedef __nv_bfloat16 bf16;
typedef __nv_bfloat162 bf162;

// ---------------- fp32 scratch ----------------
__device__ float g_r[Sc*Dc];
__device__ float g_ao[(size_t)Tc*Dc];
__device__ float g_ff[(size_t)Tc*Dc];
__device__ float g_h1[(size_t)Tc*Dc];
__device__ float g_h2[(size_t)Tc*Dc];
__device__ float g_moe[(size_t)Tc*Dc];
__device__ float g_gate[Tc];
__device__ int   g_cnt[NEc];
__device__ int   g_idx[NEc*Tc];

// ---------------- bf16 hi/lo scratch ----------------
__device__ bf16 g_qkvh[(size_t)Tc*3*Dc], g_qkvl[(size_t)Tc*3*Dc];
__device__ bf16 g_peh[Sc*Dc],  g_pel[Sc*Dc];
__device__ bf16 g_xh[(size_t)Tc*Dc],  g_xl[(size_t)Tc*Dc];
__device__ bf16 g_quh[(size_t)Tc*Dc], g_qul[(size_t)Tc*Dc];
__device__ bf16 g_qvh[(size_t)Tc*Dc], g_qvl[(size_t)Tc*Dc];
__device__ bf16 g_kh[(size_t)Tc*Dc],  g_kl[(size_t)Tc*Dc];
__device__ bf16 g_vth[(size_t)Tc*Dc], g_vtl[(size_t)Tc*Dc];
__device__ bf16 g_rh[NHc*Sc*DHc],     g_rl[NHc*Sc*DHc];
__device__ bf16 g_ctxh[(size_t)Tc*Dc], g_ctxl[(size_t)Tc*Dc];
__device__ bf16 g_h1h[(size_t)Tc*Dc], g_h1l[(size_t)Tc*Dc];
__device__ bf16 g_h2h[(size_t)Tc*Dc], g_h2l[(size_t)Tc*Dc];
__device__ bf16 g_h3h[(size_t)Tc*Dc], g_h3l[(size_t)Tc*Dc];
__device__ bf16 g_ffhh[(size_t)Tc*FFc], g_ffhl[(size_t)Tc*FFc];

// transposed split-bf16 weights: [N,K] layout, hi + lo
#define OFF_QKV  0
#define OFF_WR   3145728
#define OFF_WO   4194304
#define OFF_FF1  5242880
#define OFF_FF2  9437184
#define OFF_WE1  13631488
#define OFF_WE2  47185920
#define OFF_WOUT 80740352
#define WTOT     81788928
__device__ bf16 g_whi[WTOT];
__device__ bf16 g_wlo[WTOT];

// ---------------- helpers ----------------
__device__ __forceinline__ uint32_t smem_u32(const void* p) {
    uint32_t a;
    asm("{ .reg .u64 t; cvta.to.shared.u64 t, %1; cvt.u32.u64 %0, t; }" : "=r"(a) : "l"(p));
    return a;
}
__device__ __forceinline__ void ldm4(uint32_t* r, uint32_t a) {
    asm volatile("ldmatrix.sync.aligned.m8n8.x4.shared.b16 {%0,%1,%2,%3}, [%4];"
        : "=r"(r[0]), "=r"(r[1]), "=r"(r[2]), "=r"(r[3]) : "r"(a));
}
__device__ __forceinline__ void mma_bf16(float* c, const uint32_t* a, uint32_t b0, uint32_t b1) {
    asm volatile("mma.sync.aligned.m16n8k16.row.col.f32.bf16.bf16.f32 "
        "{%0,%1,%2,%3}, {%4,%5,%6,%7}, {%8,%9}, {%0,%1,%2,%3};"
        : "+f"(c[0]), "+f"(c[1]), "+f"(c[2]), "+f"(c[3])
        : "r"(a[0]), "r"(a[1]), "r"(a[2]), "r"(a[3]), "r"(b0), "r"(b1));
}
__device__ __forceinline__ void split1(float v, bf16& h, bf16& l) {
    h = __float2bfloat16_rn(v);
    l = __float2bfloat16_rn(v - __bfloat162float(h));
}
__device__ __forceinline__ void split2(float x, float y, bf162& h, bf162& l) {
    h = __floats2bfloat162_rn(x, y);
    float2 hf = __bfloat1622float2(h);
    l = __floats2bfloat162_rn(x - hf.x, y - hf.y);
}
#define CPA16(dst, src, sz) \
    asm volatile("cp.async.cg.shared.global [%0], [%1], 16, %2;" :: "r"(dst), "l"(src), "r"(sz))
#define CPC()  asm volatile("cp.async.commit_group;" ::: "memory")
#define CPW1() asm volatile("cp.async.wait_group 1;" ::: "memory")
#define CPW0() asm volatile("cp.async.wait_group 0;" ::: "memory")

// ---------------- weight transpose + split: W[K,N] -> hi/lo [N,K] ----------------
__global__ __launch_bounds__(256)
void wconv(const float* __restrict__ W, bf16* __restrict__ hi,
           bf16* __restrict__ lo, int K, int N)
{
    __shared__ float t[64][68];
    int tid = threadIdx.x;
    int nb = blockIdx.x * 64, kb = blockIdx.y * 64;
    size_t eoff = (size_t)blockIdx.z * K * N;

    int j  = tid & 63;
    int r0 = tid >> 6;
    #pragma unroll
    for (int l = 0; l < 16; l++) {
        int i = r0 + l * 4;
        t[j][i] = W[eoff + (size_t)(kb + i) * N + nb + j];
    }
    __syncthreads();

    int kseg = tid & 15;
    int n0t  = tid >> 4;
    #pragma unroll
    for (int l = 0; l < 4; l++) {
        int n = n0t + l * 16;
        float4 v = *(float4*)&t[n][kseg * 4];
        bf162 h0, l0, h1, l1;
        split2(v.x, v.y, h0, l0);
        split2(v.z, v.w, h1, l1);
        size_t dst = eoff + (size_t)(nb + n) * K + kb + kseg * 4;
        *(uint2*)(hi + dst) = make_uint2(*(uint32_t*)&h0, *(uint32_t*)&h1);
        *(uint2*)(lo + dst) = make_uint2(*(uint32_t*)&l0, *(uint32_t*)&l1);
    }
}

// ---------------- elementwise fp32 -> bf16 hi/lo ----------------
__global__ __launch_bounds__(256)
void econv(const float* __restrict__ src, bf16* __restrict__ hi, bf16* __restrict__ lo)
{
    size_t i = (size_t)blockIdx.x * 1024 + threadIdx.x;
    #pragma unroll
    for (int l = 0; l < 4; l++) {
        float v = src[i + l*256];
        bf16 h, lo_;
        split1(v, h, lo_);
        hi[i + l*256] = h; lo[i + l*256] = lo_;
    }
}

// ---------------- positional embedding (bf16 hi/lo) ----------------
__global__ void pe_kernel(bf16* __restrict__ peh, bf16* __restrict__ pel) {
    int i = blockIdx.x;
    float pos = (float)(Sc - 1 - i);
    #pragma unroll
    for (int l = 0; l < 4; l++) {
        int c = threadIdx.x + l * 256;
        int j = (c < Dc/2) ? c : (c - Dc/2);
        float invf = expf(-logf(10000.f) * ((float)(2*j) / (float)Dc));
        float a = pos * invf;
        float v = (c < Dc/2) ? sinf(a) : cosf(a);
        bf16 h, lo; split1(v, h, lo);
        peh[(size_t)i*Dc + c] = h; pel[(size_t)i*Dc + c] = lo;
    }
}

// ---------------- attention operand prep (reads qkv as bf16 hi+lo) ----------------
__global__ __launch_bounds__(256)
void qprep(const bf16* __restrict__ qh, const bf16* __restrict__ ql,
           const float* __restrict__ ub, const float* __restrict__ vb,
           bf16* quh, bf16* qul, bf16* qvh, bf16* qvl, bf16* kh, bf16* kl)
{
    int tok = blockIdx.x;
    int b = tok >> 10, s = tok & 1023;
    #pragma unroll
    for (int l = 0; l < 4; l++) {
        int c = threadIdx.x + l*256;
        int h = c >> 6, d = c & 63;
        size_t src = (size_t)tok*3072 + c;
        float qf = __bfloat162float(qh[src]) + __bfloat162float(ql[src]);
        float kf = __bfloat162float(qh[src + 1024]) + __bfloat162float(ql[src + 1024]);
        size_t dst = ((size_t)(b*NHc + h)*Sc + s)*64 + d;
        bf16 hh, ll;
        split1((qf + ub[c]) * 0.125f, hh, ll); quh[dst] = hh; qul[dst] = ll;
        split1((qf + vb[c]) * 0.125f, hh, ll); qvh[dst] = hh; qvl[dst] = ll;
        split1(kf, hh, ll);                   kh[dst] = hh;  kl[dst] = ll;
    }
}
__global__ __launch_bounds__(256)
void vtprep(const bf16* __restrict__ qh, const bf16* __restrict__ ql,
            bf16* vth, bf16* vtl)
{
    __shared__ float t[32][33];
    int tx = threadIdx.x & 31, ty = threadIdx.x >> 5;
    int s0 = blockIdx.x * 32, d0 = blockIdx.y * 32, bh = blockIdx.z;
    int b = bh >> 4, h = bh & 15;
    #pragma unroll
    for (int j = 0; j < 4; j++) {
        int sl = ty + j*8;
        size_t src = ((size_t)(b*Sc + s0 + sl))*3072 + 2048 + h*64 + d0 + tx;
        t[sl][tx] = __bfloat162float(qh[src]) + __bfloat162float(ql[src]);
    }
    __syncthreads();
    #pragma unroll
    for (int j = 0; j < 4; j++) {
        int dl = ty + j*8;
        float v = t[tx][dl];
        bf16 hh, ll; split1(v, hh, ll);
        size_t dst = ((size_t)bh*64 + d0 + dl)*Sc + s0 + tx;
        vth[dst] = hh; vtl[dst] = ll;
    }
}
__global__ __launch_bounds__(256)
void rprep(const float* __restrict__ r, bf16* rh, bf16* rl)
{
    int s = blockIdx.x;
    #pragma unroll
    for (int l = 0; l < 4; l++) {
        int c = threadIdx.x + l*256;
        int h = c >> 6, d = c & 63;
        float v = r[(size_t)s*Dc + c];
        bf16 hh, ll; split1(v, hh, ll);
        size_t dst = ((size_t)h*Sc + s)*64 + d;
        rh[dst] = hh; rl[dst] = ll;
    }
}

// ---------------- HMMA split-bf16 GEMM with cp.async double buffering ----------------
#define STG_BYTES 40960
#define OPD_BYTES 10240
#define TG_SMEM   (2*STG_BYTES)

template<int EPI, int OBF>
__global__ __launch_bounds__(256, 2)
void tgemm(const bf16* __restrict__ Ahi, const bf16* __restrict__ Alo,
           const bf16* __restrict__ Bhi, const bf16* __restrict__ Blo,
           float* __restrict__ C, bf16* __restrict__ Chi, bf16* __restrict__ Clo,
           int M, int N, int K,
           const float* __restrict__ bias, const float* __restrict__ rowScale,
           const int* __restrict__ gatherBase, const int* __restrict__ cntBase,
           size_t eStrideB, int eStrideBias)
{
    extern __shared__ char sm[];

    int e = blockIdx.z;
    const int* gather = gatherBase ? gatherBase + e * Tc : nullptr;
    int limit = cntBase ? cntBase[e] : M;
    int m0 = blockIdx.y * 128;
    if (m0 >= limit) return;
    int n0 = blockIdx.x * 128;
    const bf16* BhiE = Bhi + (size_t)e * eStrideB;
    const bf16* BloE = Blo + (size_t)e * eStrideB;
    const float* biasE = (EPI >= 1) ? bias + (size_t)e * eStrideBias : bias;

    int tid = threadIdx.x, wid = tid >> 5, lane = tid & 31;
    int wm = (wid & 3) * 32, wn = (wid >> 2) * 64;
    uint32_t sbase = smem_u32(sm);

    const bf16 *aph[2], *apl[2], *bph[2], *bpl[2];
    uint32_t soff[2], asz[2];
    #pragma unroll
    for (int l = 0; l < 2; l++) {
        int slot = tid + 256*l;
        int row = slot >> 2, seg = slot & 3;
        soff[l] = (uint32_t)(row * 80 + seg * 16);
        int gr = m0 + row;
        if (gr < limit) {
            int sr = gather ? gather[gr] : gr;
            aph[l] = Ahi + (size_t)sr * K + seg * 8;
            apl[l] = Alo + (size_t)sr * K + seg * 8;
            asz[l] = 16;
        } else {
            aph[l] = Ahi; apl[l] = Alo; asz[l] = 0;
        }
        size_t off = (size_t)(n0 + row) * K + seg * 8;
        bph[l] = BhiE + off; bpl[l] = BloE + off;
    }

    int t4 = lane >> 3;
    int rr = (lane & 7) + (t4 & 1) * 8;
    int cc = (t4 >> 1) * 8;

    float acc[2][8][4];
    #pragma unroll
    for (int i = 0; i < 2; i++)
        #pragma unroll
        for (int j = 0; j < 8; j++)
            #pragma unroll
            for (int q = 0; q < 4; q++) acc[i][j][q] = 0.f;

    int Kc = K >> 5;

    #pragma unroll
    for (int s = 0; s < 2; s++) {
        if (s < Kc) {
            uint32_t b = sbase + s * STG_BYTES;
            int ko = s * 32;
            #pragma unroll
            for (int l = 0; l < 2; l++) {
                CPA16(b + soff[l],               aph[l] + ko, asz[l]);
                CPA16(b + OPD_BYTES + soff[l],   apl[l] + ko, asz[l]);
                CPA16(b + 2*OPD_BYTES + soff[l], bph[l] + ko, 16u);
                CPA16(b + 3*OPD_BYTES + soff[l], bpl[l] + ko, 16u);
            }
            CPC();
        }
    }

    for (int c = 0; c < Kc; c++) {
        if (c + 1 < Kc) { CPW1(); } else { CPW0(); }
        __syncthreads();

        uint32_t sb = sbase + (uint32_t)(c & 1) * STG_BYTES;
        uint32_t baAH = sb, baAL = sb + OPD_BYTES;
        uint32_t baBH = sb + 2*OPD_BYTES, baBL = sb + 3*OPD_BYTES;

        #pragma unroll
        for (int k16 = 0; k16 < 32; k16 += 16) {
            uint32_t aH[2][4], aL[2][4];
            #pragma unroll
            for (int mi = 0; mi < 2; mi++) {
                uint32_t off = ((uint32_t)(wm + mi*16 + rr) * 40u + (uint32_t)(k16 + cc)) * 2u;
                ldm4(aH[mi], baAH + off);
                ldm4(aL[mi], baAL + off);
            }
            uint32_t bH[4][4], bL[4][4];
            #pragma unroll
            for (int ni = 0; ni < 4; ni++) {
                uint32_t off = ((uint32_t)(wn + ni*16 + rr) * 40u + (uint32_t)(k16 + cc)) * 2u;
                ldm4(bH[ni], baBH + off);
                ldm4(bL[ni], baBL + off);
            }
            #pragma unroll
            for (int mi = 0; mi < 2; mi++)
                #pragma unroll
                for (int ni = 0; ni < 4; ni++)
                    #pragma unroll
                    for (int h = 0; h < 2; h++) {
                        int j = ni*2 + h;
                        mma_bf16(acc[mi][j], aH[mi], bH[ni][h], bH[ni][h+2]);
                        mma_bf16(acc[mi][j], aH[mi], bL[ni][h], bL[ni][h+2]);
                        mma_bf16(acc[mi][j], aL[mi], bH[ni][h], bH[ni][h+2]);
                    }
        }
        __syncthreads();

        if (c + 2 < Kc) {
            uint32_t b = sbase + (uint32_t)(c & 1) * STG_BYTES;
            int ko = (c + 2) * 32;
            #pragma unroll
            for (int l = 0; l < 2; l++) {
                CPA16(b + soff[l],               aph[l] + ko, asz[l]);
                CPA16(b + OPD_BYTES + soff[l],   apl[l] + ko, asz[l]);
                CPA16(b + 2*OPD_BYTES + soff[l], bph[l] + ko, 16u);
                CPA16(b + 3*OPD_BYTES + soff[l], bpl[l] + ko, 16u);
            }
            CPC();
        }
    }

    #pragma unroll
    for (int mi = 0; mi < 2; mi++) {
        #pragma unroll
        for (int half = 0; half < 2; half++) {
            int gr = m0 + wm + mi*16 + (lane >> 2) + half*8;
            if (gr >= limit) continue;
            int crow = gather ? gather[gr] : gr;
            float rs = 1.f;
            if (EPI == 3) rs = rowScale[crow];
            #pragma unroll
            for (int j = 0; j < 8; j++) {
                int col = n0 + wn + j*8 + (lane & 3)*2;
                float vx = acc[mi][j][half*2 + 0];
                float vy = acc[mi][j][half*2 + 1];
                if (EPI >= 1) { vx += biasE[col]; vy += biasE[col+1]; }
                if (EPI == 2) { vx = fmaxf(vx, 0.f); vy = fmaxf(vy, 0.f); }
                if (EPI == 3) { vx *= rs; vy *= rs; }
                if (OBF == 0) {
                    *(float2*)(C + (size_t)crow * N + col) = make_float2(vx, vy);
                } else {
                    bf162 h, l; split2(vx, vy, h, l);
                    *(bf162*)(Chi + (size_t)crow * N + col) = h;
                    *(bf162*)(Clo + (size_t)crow * N + col) = l;
                }
            }
        }
    }
}

// ---------------- fused TXL attention ----------------
#define FA_QUH 0
#define FA_QUL 9216
#define FA_QVH 18432
#define FA_QVL 27648
#define FA_KH  36864
#define FA_KL  46080
#define FA_RH  55296
#define FA_RL  73728
#define FA_VH  92160
#define FA_VL  101376
#define FA_PH  110592
#define FA_PL  119808
#define FA_BD  129024
#define FA_RED (FA_BD + 33792)
#define FA_SMEM (FA_RED + 1024)

__global__ __launch_bounds__(256, 1)
void fattn(const bf16* __restrict__ quh, const bf16* __restrict__ qul,
           const bf16* __restrict__ qvh, const bf16* __restrict__ qvl,
           const bf16* __restrict__ kh,  const bf16* __restrict__ kl,
           const bf16* __restrict__ rhp, const bf16* __restrict__ rlp,
           const bf16* __restrict__ vth, const bf16* __restrict__ vtl,
           bf16* __restrict__ ctxh, bf16* __restrict__ ctxl)
{
    extern __shared__ char sm[];
    int qt = 15 - blockIdx.x;
    int bh = blockIdx.y;
    int b = bh >> 4, h = bh & 15;
    int q0 = qt * 64;
    uint32_t sb = smem_u32(sm);
    int tid = threadIdx.x, wid = tid >> 5, lane = tid & 31;
    int wm = (wid & 3) * 16, wn = (wid >> 2) * 32;
    int wcol = wid >> 2;
    int t4l = lane >> 3;
    int rr = (lane & 7) + (t4l & 1) * 8;
    int cc = (t4l >> 1) * 8;
    int qrow = (lane >> 2);
    int kc0 = (lane & 3) * 2;

    #pragma unroll
    for (int i = 0; i < 2; i++) {
        int slot = tid + 256*i;
        int row = slot >> 3, seg = slot & 7;
        size_t g = ((size_t)bh*Sc + q0 + row)*64 + seg*8;
        *(uint4*)(sm + FA_QUH + row*144 + seg*16) = *(const uint4*)(quh + g);
        *(uint4*)(sm + FA_QUL + row*144 + seg*16) = *(const uint4*)(qul + g);
        *(uint4*)(sm + FA_QVH + row*144 + seg*16) = *(const uint4*)(qvh + g);
        *(uint4*)(sm + FA_QVL + row*144 + seg*16) = *(const uint4*)(qvl + g);
    }

    float mrow[2] = {-1e30f, -1e30f}, lrow[2] = {0.f, 0.f};
    float oacc[4][4];
    #pragma unroll
    for (int j = 0; j < 4; j++)
        #pragma unroll
        for (int q = 0; q < 4; q++) oacc[j][q] = 0.f;

    for (int kt = 0; kt <= qt; kt++) {
        int k0 = kt * 64;
        int t0 = kt - qt + 15;
        __syncthreads();

        #pragma unroll
        for (int i = 0; i < 2; i++) {
            int slot = tid + 256*i;
            int row = slot >> 3, seg = slot & 7;
            size_t gk = ((size_t)bh*Sc + k0 + row)*64 + seg*8;
            *(uint4*)(sm + FA_KH + row*144 + seg*16) = *(const uint4*)(kh + gk);
            *(uint4*)(sm + FA_KL + row*144 + seg*16) = *(const uint4*)(kl + gk);
            size_t gv = ((size_t)bh*64 + row)*Sc + k0 + seg*8;
            *(uint4*)(sm + FA_VH + row*144 + seg*16) = *(const uint4*)(vth + gv);
            *(uint4*)(sm + FA_VL + row*144 + seg*16) = *(const uint4*)(vtl + gv);
        }
        int tfrom = (kt == 0) ? t0 : t0 + 1;
        for (int t = tfrom; t <= t0 + 1 && t <= 15; t++) {
            int hoff = (t & 1) * 64;
            #pragma unroll
            for (int i = 0; i < 2; i++) {
                int slot = tid + 256*i;
                int row = slot >> 3, seg = slot & 7;
                size_t gr = ((size_t)h*Sc + t*64 + row)*64 + seg*8;
                *(uint4*)(sm + FA_RH + (hoff + row)*144 + seg*16) = *(const uint4*)(rhp + gr);
                *(uint4*)(sm + FA_RL + (hoff + row)*144 + seg*16) = *(const uint4*)(rlp + gr);
            }
        }
        __syncthreads();

        for (int t = tfrom; t <= t0 + 1 && t <= 15; t++) {
            int hoff = (t & 1) * 64;
            float bacc[4][4];
            #pragma unroll
            for (int j = 0; j < 4; j++)
                #pragma unroll
                for (int q = 0; q < 4; q++) bacc[j][q] = 0.f;
            #pragma unroll
            for (int k16 = 0; k16 < 64; k16 += 16) {
                uint32_t aH[4], aL[4];
                uint32_t offA = ((uint32_t)(wm + rr) * 72u + (uint32_t)(k16 + cc)) * 2u;
                ldm4(aH, sb + FA_QVH + offA);
                ldm4(aL, sb + FA_QVL + offA);
                uint32_t bH[2][4], bL[2][4];
                #pragma unroll
                for (int ni = 0; ni < 2; ni++) {
                    uint32_t offB = ((uint32_t)(hoff + wn + ni*16 + rr) * 72u + (uint32_t)(k16 + cc)) * 2u;
                    ldm4(bH[ni], sb + FA_RH + offB);
                    ldm4(bL[ni], sb + FA_RL + offB);
                }
                #pragma unroll
                for (int ni = 0; ni < 2; ni++)
                    #pragma unroll
                    for (int hb = 0; hb < 2; hb++) {
                        int j = ni*2 + hb;
                        mma_bf16(bacc[j], aH, bH[ni][hb], bH[ni][hb+2]);
                        mma_bf16(bacc[j], aH, bL[ni][hb], bL[ni][hb+2]);
                        mma_bf16(bacc[j], aL, bH[ni][hb], bH[ni][hb+2]);
                    }
            }
            #pragma unroll
            for (int half = 0; half < 2; half++) {
                int row = wm + qrow + half*8;
                #pragma unroll
                for (int j = 0; j < 4; j++) {
                    int col = hoff + wn + j*8 + kc0;
                    *(float2*)(sm + FA_BD + row*528 + col*4) =
                        make_float2(bacc[j][half*2], bacc[j][half*2+1]);
                }
            }
        }

        float s[4][4];
        #pragma unroll
        for (int j = 0; j < 4; j++)
            #pragma unroll
            for (int q = 0; q < 4; q++) s[j][q] = 0.f;
        #pragma unroll
        for (int k16 = 0; k16 < 64; k16 += 16) {
            uint32_t aH[4], aL[4];
            uint32_t offA = ((uint32_t)(wm + rr) * 72u + (uint32_t)(k16 + cc)) * 2u;
            ldm4(aH, sb + FA_QUH + offA);
            ldm4(aL, sb + FA_QUL + offA);
            uint32_t bH[2][4], bL[2][4];
            #pragma unroll
            for (int ni = 0; ni < 2; ni++) {
                uint32_t offB = ((uint32_t)(wn + ni*16 + rr) * 72u + (uint32_t)(k16 + cc)) * 2u;
                ldm4(bH[ni], sb + FA_KH + offB);
                ldm4(bL[ni], sb + FA_KL + offB);
            }
            #pragma unroll
            for (int ni = 0; ni < 2; ni++)
                #pragma unroll
                for (int hb = 0; hb < 2; hb++) {
                    int j = ni*2 + hb;
                    mma_bf16(s[j], aH, bH[ni][hb], bH[ni][hb+2]);
                    mma_bf16(s[j], aH, bL[ni][hb], bL[ni][hb+2]);
                    mma_bf16(s[j], aL, bH[ni][hb], bH[ni][hb+2]);
                }
        }
        __syncthreads();

        bool diag = (kt == qt);
        int ringbase = (t0 & 1) * 64;
        float mt2[2], sc2[2], rs2[2];

        #pragma unroll
        for (int half = 0; half < 2; half++) {
            int row = wm + qrow + half*8;
            float mt = -1e30f;
            #pragma unroll
            for (int j = 0; j < 4; j++) {
                #pragma unroll
                for (int c2 = 0; c2 < 2; c2++) {
                    int colk = wn + j*8 + kc0 + c2;
                    int jcol = colk - row + 63;
                    int phys = (ringbase + jcol) & 127;
                    float val = s[j][half*2 + c2] +
                        *(const float*)(sm + FA_BD + row*528 + phys*4);
                    if (diag && colk > row) val = -1e30f;
                    s[j][half*2 + c2] = val;
                    mt = fmaxf(mt, val);
                }
            }
            mt = fmaxf(mt, __shfl_xor_sync(0xFFFFFFFFu, mt, 1));
            mt = fmaxf(mt, __shfl_xor_sync(0xFFFFFFFFu, mt, 2));
            mt2[half] = mt;
            if ((lane & 3) == 0)
                *(float*)(sm + FA_RED + (wcol*64 + row)*4) = mt;
        }
        __syncthreads();

        #pragma unroll
        for (int half = 0; half < 2; half++) {
            int row = wm + qrow + half*8;
            float other = *(const float*)(sm + FA_RED + ((1-wcol)*64 + row)*4);
            float mnew = fmaxf(mrow[half], fmaxf(mt2[half], other));
            float scale = __expf(mrow[half] - mnew);
            sc2[half] = scale;
            float rs = 0.f;
            #pragma unroll
            for (int j = 0; j < 4; j++) {
                #pragma unroll
                for (int c2 = 0; c2 < 2; c2++) {
                    float p = __expf(s[j][half*2 + c2] - mnew);
                    s[j][half*2 + c2] = p;
                    rs += p;
                }
            }
            rs += __shfl_xor_sync(0xFFFFFFFFu, rs, 1);
            rs += __shfl_xor_sync(0xFFFFFFFFu, rs, 2);
            rs2[half] = rs;
            if ((lane & 3) == 0)
                *(float*)(sm + FA_RED + 512 + (wcol*64 + row)*4) = rs;
            mrow[half] = mnew;
            #pragma unroll
            for (int j = 0; j < 4; j++) {
                oacc[j][half*2 + 0] *= scale;
                oacc[j][half*2 + 1] *= scale;
            }
            #pragma unroll
            for (int j = 0; j < 4; j++) {
                int col = wn + j*8 + kc0;
                bf162 hh, ll;
                split2(s[j][half*2], s[j][half*2+1], hh, ll);
                *(bf162*)(sm + FA_PH + row*144 + col*2) = hh;
                *(bf162*)(sm + FA_PL + row*144 + col*2) = ll;
            }
        }
        __syncthreads();

        #pragma unroll
        for (int half = 0; half < 2; half++) {
            int row = wm + qrow + half*8;
            float other = *(const float*)(sm + FA_RED + 512 + ((1-wcol)*64 + row)*4);
            lrow[half] = lrow[half] * sc2[half] + rs2[half] + other;
        }

        #pragma unroll
        for (int k16 = 0; k16 < 64; k16 += 16) {
            uint32_t aH[4], aL[4];
            uint32_t offA = ((uint32_t)(wm + rr) * 72u + (uint32_t)(k16 + cc)) * 2u;
            ldm4(aH, sb + FA_PH + offA);
            ldm4(aL, sb + FA_PL + offA);
            uint32_t bH[2][4], bL[2][4];
            #pragma unroll
            for (int ni = 0; ni < 2; ni++) {
                uint32_t offB = ((uint32_t)(wn + ni*16 + rr) * 72u + (uint32_t)(k16 + cc)) * 2u;
                ldm4(bH[ni], sb + FA_VH + offB);
                ldm4(bL[ni], sb + FA_VL + offB);
            }
            #pragma unroll
            for (int ni = 0; ni < 2; ni++)
                #pragma unroll
                for (int hb = 0; hb < 2; hb++) {
                    int j = ni*2 + hb;
                    mma_bf16(oacc[j], aH, bH[ni][hb], bH[ni][hb+2]);
                    mma_bf16(oacc[j], aH, bL[ni][hb], bL[ni][hb+2]);
                    mma_bf16(oacc[j], aL, bH[ni][hb], bH[ni][hb+2]);
                }
        }
    }

    #pragma unroll
    for (int half = 0; half < 2; half++) {
        int row = wm + qrow + half*8;
        int tok = b*Sc + q0 + row;
        float inv = 1.f / lrow[half];
        #pragma unroll
        for (int j = 0; j < 4; j++) {
            int col = h*64 + wn + j*8 + kc0;
            bf162 hh, ll;
            split2(oacc[j][half*2] * inv, oacc[j][half*2+1] * inv, hh, ll);
            *(bf162*)(ctxh + (size_t)tok*Dc + col) = hh;
            *(bf162*)(ctxl + (size_t)tok*Dc + col) = ll;
        }
    }
}

// ---------------- residual + layernorm ----------------
// OBF: 0 = fp32 only, 1 = fp32 + bf16 hi/lo, 2 = bf16 hi/lo only
template<int OBF>
__global__ __launch_bounds__(256)
void rln_k(const float* __restrict__ x, const float* __restrict__ y,
           const float* __restrict__ g, const float* __restrict__ bta,
           float* __restrict__ out, bf16* __restrict__ oh, bf16* __restrict__ ol)
{
    int row = blockIdx.x;
    int tid = threadIdx.x;
    __shared__ float red[256];
    float v[4];
    float s = 0.f, ss = 0.f;
    #pragma unroll
    for (int l = 0; l < 4; l++) {
        size_t idx = (size_t)row*Dc + tid + l*256;
        float val = x[idx] + y[idx];
        v[l] = val; s += val; ss += val*val;
    }
    red[tid] = s; __syncthreads();
    for (int st = 128; st > 0; st >>= 1) { if (tid < st) red[tid] += red[tid+st]; __syncthreads(); }
    float mean = red[0] * (1.f/Dc); __syncthreads();
    red[tid] = ss; __syncthreads();
    for (int st = 128; st > 0; st >>= 1) { if (tid < st) red[tid] += red[tid+st]; __syncthreads(); }
    float var = red[0] * (1.f/Dc) - mean*mean;
    float inv = rsqrtf(var + 1e-5f);
    #pragma unroll
    for (int l = 0; l < 4; l++) {
        int c = tid + l*256;
        float o = (v[l] - mean) * inv * g[c] + bta[c];
        if (OBF != 2) out[(size_t)row*Dc + c] = o;
        if (OBF >= 1) {
            bf16 hh, ll; split1(o, hh, ll);
            oh[(size_t)row*Dc + c] = hh;
            ol[(size_t)row*Dc + c] = ll;
        }
    }
}

// ---------------- router ----------------
__global__ void zero_cnt(int* cnt) { if (threadIdx.x < NEc) cnt[threadIdx.x] = 0; }

__global__ __launch_bounds__(256)
void router_k(const float* __restrict__ h2, const float* __restrict__ Wg,
              float* __restrict__ gate, int* __restrict__ cnt, int* __restrict__ idxlist)
{
    int warp = (blockIdx.x * blockDim.x + threadIdx.x) >> 5;
    int lane = threadIdx.x & 31;
    if (warp >= Tc) return;
    const float* hrow = h2 + (size_t)warp * Dc;
    float logit[NEc];
    #pragma unroll
    for (int e = 0; e < NEc; e++) {
        float p = 0.f;
        for (int d = lane; d < Dc; d += 32) p += hrow[d] * Wg[d*NEc + e];
        #pragma unroll
        for (int off = 16; off > 0; off >>= 1) p += __shfl_xor_sync(0xFFFFFFFFu, p, off);
        logit[e] = p;
    }
    float m = logit[0]; int am = 0;
    #pragma unroll
    for (int e = 1; e < NEc; e++) if (logit[e] > m) { m = logit[e]; am = e; }
    float sum = 0.f;
    #pragma unroll
    for (int e = 0; e < NEc; e++) sum += expf(logit[e] - m);
    if (lane == 0) {
        gate[warp] = 1.f / sum;
        int pos = atomicAdd(&cnt[am], 1);
        idxlist[am*Tc + pos] = warp;
    }
}

// ---------------- launch ----------------
extern "C" void kernel_launch(void* const* d_in, const int* in_sizes, int n_in,
                              void* d_out, int out_size)
{
    const float* x    = (const float*)d_in[0];
    const float* Wqkv = (const float*)d_in[1];
    const float* Wo   = (const float*)d_in[2];
    const float* Wr   = (const float*)d_in[3];
    const float* u_b  = (const float*)d_in[4];
    const float* v_b  = (const float*)d_in[5];
    const float* ln1g = (const float*)d_in[6];
    const float* ln1b = (const float*)d_in[7];
    const float* Wff1 = (const float*)d_in[8];
    const float* bff1 = (const float*)d_in[9];
    const float* Wff2 = (const float*)d_in[10];
    const float* bff2 = (const float*)d_in[11];
    const float* ln2g = (const float*)d_in[12];
    const float* ln2b = (const float*)d_in[13];
    const float* Wg   = (const float*)d_in[14];
    const float* We1  = (const float*)d_in[15];
    const float* be1  = (const float*)d_in[16];
    const float* We2  = (const float*)d_in[17];
    const float* be2  = (const float*)d_in[18];
    const float* ln3g = (const float*)d_in[19];
    const float* ln3b = (const float*)d_in[20];
    const float* Wout = (const float*)d_in[21];
    float* out = (float*)d_out;

    static int inited = 0;
    if (!inited) {
        cudaFuncSetAttribute(tgemm<0,0>, cudaFuncAttributeMaxDynamicSharedMemorySize, TG_SMEM);
        cudaFuncSetAttribute(tgemm<0,1>, cudaFuncAttributeMaxDynamicSharedMemorySize, TG_SMEM);
        cudaFuncSetAttribute(tgemm<1,0>, cudaFuncAttributeMaxDynamicSharedMemorySize, TG_SMEM);
        cudaFuncSetAttribute(tgemm<2,1>, cudaFuncAttributeMaxDynamicSharedMemorySize, TG_SMEM);
        cudaFuncSetAttribute(tgemm<3,0>, cudaFuncAttributeMaxDynamicSharedMemorySize, TG_SMEM);
        cudaFuncSetAttribute(fattn,      cudaFuncAttributeMaxDynamicSharedMemorySize, FA_SMEM);
        inited = 1;
    }

    float *r, *ao, *ff, *h1, *h2, *moe, *gate;
    int *cnt, *idx;
    bf16 *whi, *wlo, *peh, *pel, *xh, *xl, *qkvh, *qkvl;
    bf16 *quh, *qul, *qvh, *qvl, *kh, *kl, *vth, *vtl, *rh, *rl;
    bf16 *ctxh, *ctxl, *h1h, *h1l, *h2h, *h2l, *h3h, *h3l, *ffhh, *ffhl;

    cudaGetSymbolAddress((void**)&r,   g_r);
    cudaGetSymbolAddress((void**)&ao,  g_ao);
    cudaGetSymbolAddress((void**)&ff,  g_ff);
    cudaGetSymbolAddress((void**)&h1,  g_h1);
    cudaGetSymbolAddress((void**)&h2,  g_h2);
    cudaGetSymbolAddress((void**)&moe, g_moe);
    cudaGetSymbolAddress((void**)&gate,g_gate);
    cudaGetSymbolAddress((void**)&cnt, g_cnt);
    cudaGetSymbolAddress((void**)&idx, g_idx);
    cudaGetSymbolAddress((void**)&whi, g_whi);
    cudaGetSymbolAddress((void**)&wlo, g_wlo);
    cudaGetSymbolAddress((void**)&peh, g_peh);
    cudaGetSymbolAddress((void**)&pel, g_pel);
    cudaGetSymbolAddress((void**)&xh,  g_xh);
    cudaGetSymbolAddress((void**)&xl,  g_xl);
    cudaGetSymbolAddress((void**)&qkvh,g_qkvh);
    cudaGetSymbolAddress((void**)&qkvl,g_qkvl);
    cudaGetSymbolAddress((void**)&quh, g_quh);
    cudaGetSymbolAddress((void**)&qul, g_qul);
    cudaGetSymbolAddress((void**)&qvh, g_qvh);
    cudaGetSymbolAddress((void**)&qvl, g_qvl);
    cudaGetSymbolAddress((void**)&kh,  g_kh);
    cudaGetSymbolAddress((void**)&kl,  g_kl);
    cudaGetSymbolAddress((void**)&vth, g_vth);
    cudaGetSymbolAddress((void**)&vtl, g_vtl);
    cudaGetSymbolAddress((void**)&rh,  g_rh);
    cudaGetSymbolAddress((void**)&rl,  g_rl);
    cudaGetSymbolAddress((void**)&ctxh,g_ctxh);
    cudaGetSymbolAddress((void**)&ctxl,g_ctxl);
    cudaGetSymbolAddress((void**)&h1h, g_h1h);
    cudaGetSymbolAddress((void**)&h1l, g_h1l);
    cudaGetSymbolAddress((void**)&h2h, g_h2h);
    cudaGetSymbolAddress((void**)&h2l, g_h2l);
    cudaGetSymbolAddress((void**)&h3h, g_h3h);
    cudaGetSymbolAddress((void**)&h3l, g_h3l);
    cudaGetSymbolAddress((void**)&ffhh,g_ffhh);
    cudaGetSymbolAddress((void**)&ffhl,g_ffhl);

    // weight transpose + split
    wconv<<<dim3(3072/64, 1024/64), 256>>>(Wqkv, whi+OFF_QKV,  wlo+OFF_QKV,  1024, 3072);
    wconv<<<dim3(1024/64, 1024/64), 256>>>(Wr,   whi+OFF_WR,   wlo+OFF_WR,   1024, 1024);
    wconv<<<dim3(1024/64, 1024/64), 256>>>(Wo,   whi+OFF_WO,   wlo+OFF_WO,   1024, 1024);
    wconv<<<dim3(4096/64, 1024/64), 256>>>(Wff1, whi+OFF_FF1,  wlo+OFF_FF1,  1024, 4096);
    wconv<<<dim3(1024/64, 4096/64), 256>>>(Wff2, whi+OFF_FF2,  wlo+OFF_FF2,  4096, 1024);
    wconv<<<dim3(1024/64, 1024/64), 256>>>(Wout, whi+OFF_WOUT, wlo+OFF_WOUT, 1024, 1024);
    wconv<<<dim3(4096/64, 1024/64, NEc), 256>>>(We1, whi+OFF_WE1, wlo+OFF_WE1, 1024, 4096);
    wconv<<<dim3(1024/64, 4096/64, NEc), 256>>>(We2, whi+OFF_WE2, wlo+OFF_WE2, 4096, 1024);

    pe_kernel<<<Sc, 256>>>(peh, pel);
    econv<<<Tc, 256>>>(x, xh, xl);

    // projections (QKV emitted as bf16 hi/lo)
    tgemm<0,1><<<dim3(3072/128, Tc/128), 256, TG_SMEM>>>(xh, xl, whi+OFF_QKV, wlo+OFF_QKV,
        nullptr, qkvh, qkvl, Tc, 3072, 1024, nullptr, nullptr, nullptr, nullptr, 0, 0);
    tgemm<0,0><<<dim3(1024/128, Sc/128), 256, TG_SMEM>>>(peh, pel, whi+OFF_WR, wlo+OFF_WR,
        r, nullptr, nullptr, Sc, 1024, 1024, nullptr, nullptr, nullptr, nullptr, 0, 0);

    // attention prep
    qprep<<<Tc, 256>>>(qkvh, qkvl, u_b, v_b, quh, qul, qvh, qvl, kh, kl);
    vtprep<<<dim3(Sc/32, 2, BHc), 256>>>(qkvh, qkvl, vth, vtl);
    rprep<<<Sc, 256>>>(r, rh, rl);

    // fused attention
    fattn<<<dim3(16, BHc), 256, FA_SMEM>>>(quh, qul, qvh, qvl, kh, kl, rh, rl,
                                           vth, vtl, ctxh, ctxl);
    tgemm<0,0><<<dim3(1024/128, Tc/128), 256, TG_SMEM>>>(ctxh, ctxl, whi+OFF_WO, wlo+OFF_WO,
        ao, nullptr, nullptr, Tc, 1024, 1024, nullptr, nullptr, nullptr, nullptr, 0, 0);
    rln_k<1><<<Tc, 256>>>(x, ao, ln1g, ln1b, h1, h1h, h1l);

    // FFN
    tgemm<2,1><<<dim3(4096/128, Tc/128), 256, TG_SMEM>>>(h1h, h1l, whi+OFF_FF1, wlo+OFF_FF1,
        nullptr, ffhh, ffhl, Tc, 4096, 1024, bff1, nullptr, nullptr, nullptr, 0, 0);
    tgemm<1,0><<<dim3(1024/128, Tc/128), 256, TG_SMEM>>>(ffhh, ffhl, whi+OFF_FF2, wlo+OFF_FF2,
        ff, nullptr, nullptr, Tc, 1024, 4096, bff2, nullptr, nullptr, nullptr, 0, 0);
    rln_k<1><<<Tc, 256>>>(h1, ff, ln2g, ln2b, h2, h2h, h2l);

    // MoE
    zero_cnt<<<1, 32>>>(cnt);
    router_k<<<Tc/8, 256>>>(h2, Wg, gate, cnt, idx);
    tgemm<2,1><<<dim3(4096/128, Tc/128, NEc), 256, TG_SMEM>>>(
        h2h, h2l, whi+OFF_WE1, wlo+OFF_WE1,
        nullptr, ffhh, ffhl, Tc, 4096, 1024, be1, nullptr, idx, cnt,
        (size_t)FFc*Dc, FFc);
    tgemm<3,0><<<dim3(1024/128, Tc/128, NEc), 256, TG_SMEM>>>(
        ffhh, ffhl, whi+OFF_WE2, wlo+OFF_WE2,
        moe, nullptr, nullptr, Tc, 1024, 4096, be2, gate, idx, cnt,
        (size_t)Dc*FFc, Dc);
    rln_k<2><<<Tc, 256>>>(h2, moe, ln3g, ln3b, nullptr, h3h, h3l);

    // output projection
    tgemm<0,0><<<dim3(1024/128, Tc/128), 256, TG_SMEM>>>(h3h, h3l, whi+OFF_WOUT, wlo+OFF_WOUT,
        out, nullptr, nullptr, Tc, 1024, 1024, nullptr, nullptr, nullptr, nullptr, 0, 0);
}

// round 16
// speedup vs baseline: 1.0712x; 1.0062x over previous
#include <cuda_runtime.h>
#include <cuda_bf16.h>
#include <math.h>
#include <stdint.h>

#define Bc 4
#define Sc 1024
#define Dc 1024
#define NHc 16
#define DHc 64
#define FFc 4096
#define NEc 8
#define Tc (Bc*Sc)
#define BHc (Bc*NHc)

typedef __nv_bfloat16 bf16;
typedef __nv_bfloat162 bf162;

// ---------------- fp32 scratch ----------------
__device__ float g_qkv[(size_t)Tc*3*Dc];
__device__ float g_r[Sc*Dc];
__device__ float g_ao[(size_t)Tc*Dc];
__device__ float g_ff[(size_t)Tc*Dc];
__device__ float g_h1[(size_t)Tc*Dc];
__device__ float g_h2[(size_t)Tc*Dc];
__device__ float g_moe[(size_t)Tc*Dc];
__device__ float g_gate[Tc];
__device__ int   g_cnt[NEc];
__device__ int   g_idx[NEc*Tc];

// ---------------- bf16 hi/lo scratch ----------------
__device__ bf16 g_peh[Sc*Dc],  g_pel[Sc*Dc];
__device__ bf16 g_xh[(size_t)Tc*Dc],  g_xl[(size_t)Tc*Dc];
__device__ bf16 g_quh[(size_t)Tc*Dc], g_qul[(size_t)Tc*Dc];
__device__ bf16 g_qvh[(size_t)Tc*Dc], g_qvl[(size_t)Tc*Dc];
__device__ bf16 g_kh[(size_t)Tc*Dc],  g_kl[(size_t)Tc*Dc];
__device__ bf16 g_vth[(size_t)Tc*Dc], g_vtl[(size_t)Tc*Dc];
__device__ bf16 g_rh[NHc*Sc*DHc],     g_rl[NHc*Sc*DHc];
__device__ bf16 g_ctxh[(size_t)Tc*Dc], g_ctxl[(size_t)Tc*Dc];
__device__ bf16 g_h1h[(size_t)Tc*Dc], g_h1l[(size_t)Tc*Dc];
__device__ bf16 g_h2h[(size_t)Tc*Dc], g_h2l[(size_t)Tc*Dc];
__device__ bf16 g_h3h[(size_t)Tc*Dc], g_h3l[(size_t)Tc*Dc];
__device__ bf16 g_ffhh[(size_t)Tc*FFc], g_ffhl[(size_t)Tc*FFc];

// transposed split-bf16 weights: [N,K] layout, hi + lo
#define OFF_QKV  0
#define OFF_WR   3145728
#define OFF_WO   4194304
#define OFF_FF1  5242880
#define OFF_FF2  9437184
#define OFF_WE1  13631488
#define OFF_WE2  47185920
#define OFF_WOUT 80740352
#define WTOT     81788928
__device__ bf16 g_whi[WTOT];
__device__ bf16 g_wlo[WTOT];

// ---------------- helpers ----------------
__device__ __forceinline__ uint32_t smem_u32(const void* p) {
    uint32_t a;
    asm("{ .reg .u64 t; cvta.to.shared.u64 t, %1; cvt.u32.u64 %0, t; }" : "=r"(a) : "l"(p));
    return a;
}
__device__ __forceinline__ void ldm4(uint32_t* r, uint32_t a) {
    asm volatile("ldmatrix.sync.aligned.m8n8.x4.shared.b16 {%0,%1,%2,%3}, [%4];"
        : "=r"(r[0]), "=r"(r[1]), "=r"(r[2]), "=r"(r[3]) : "r"(a));
}
__device__ __forceinline__ void mma_bf16(float* c, const uint32_t* a, uint32_t b0, uint32_t b1) {
    asm volatile("mma.sync.aligned.m16n8k16.row.col.f32.bf16.bf16.f32 "
        "{%0,%1,%2,%3}, {%4,%5,%6,%7}, {%8,%9}, {%0,%1,%2,%3};"
        : "+f"(c[0]), "+f"(c[1]), "+f"(c[2]), "+f"(c[3])
        : "r"(a[0]), "r"(a[1]), "r"(a[2]), "r"(a[3]), "r"(b0), "r"(b1));
}
__device__ __forceinline__ void split1(float v, bf16& h, bf16& l) {
    h = __float2bfloat16_rn(v);
    l = __float2bfloat16_rn(v - __bfloat162float(h));
}
__device__ __forceinline__ void split2(float x, float y, bf162& h, bf162& l) {
    h = __floats2bfloat162_rn(x, y);
    float2 hf = __bfloat1622float2(h);
    l = __floats2bfloat162_rn(x - hf.x, y - hf.y);
}
#define CPA16(dst, src, sz) \
    asm volatile("cp.async.cg.shared.global [%0], [%1], 16, %2;" :: "r"(dst), "l"(src), "r"(sz))
#define CPC()  asm volatile("cp.async.commit_group;" ::: "memory")
#define CPW1() asm volatile("cp.async.wait_group 1;" ::: "memory")
#define CPW0() asm volatile("cp.async.wait_group 0;" ::: "memory")

// ---------------- weight transpose + split: W[K,N] -> hi/lo [N,K] ----------------
__global__ __launch_bounds__(256)
void wconv(const float* __restrict__ W, bf16* __restrict__ hi,
           bf16* __restrict__ lo, int K, int N)
{
    __shared__ float t[64][68];
    int tid = threadIdx.x;
    int nb = blockIdx.x * 64, kb = blockIdx.y * 64;
    size_t eoff = (size_t)blockIdx.z * K * N;

    int j  = tid & 63;
    int r0 = tid >> 6;
    #pragma unroll
    for (int l = 0; l < 16; l++) {
        int i = r0 + l * 4;
        t[j][i] = W[eoff + (size_t)(kb + i) * N + nb + j];
    }
    __syncthreads();

    int kseg = tid & 15;
    int n0t  = tid >> 4;
    #pragma unroll
    for (int l = 0; l < 4; l++) {
        int n = n0t + l * 16;
        float4 v = *(float4*)&t[n][kseg * 4];
        bf162 h0, l0, h1, l1;
        split2(v.x, v.y, h0, l0);
        split2(v.z, v.w, h1, l1);
        size_t dst = eoff + (size_t)(nb + n) * K + kb + kseg * 4;
        *(uint2*)(hi + dst) = make_uint2(*(uint32_t*)&h0, *(uint32_t*)&h1);
        *(uint2*)(lo + dst) = make_uint2(*(uint32_t*)&l0, *(uint32_t*)&l1);
    }
}

// ---------------- elementwise fp32 -> bf16 hi/lo ----------------
__global__ __launch_bounds__(256)
void econv(const float* __restrict__ src, bf16* __restrict__ hi, bf16* __restrict__ lo)
{
    size_t i = (size_t)blockIdx.x * 1024 + threadIdx.x;
    #pragma unroll
    for (int l = 0; l < 4; l++) {
        float v = src[i + l*256];
        bf16 h, lo_;
        split1(v, h, lo_);
        hi[i + l*256] = h; lo[i + l*256] = lo_;
    }
}

// ---------------- positional embedding (bf16 hi/lo) ----------------
__global__ void pe_kernel(bf16* __restrict__ peh, bf16* __restrict__ pel) {
    int i = blockIdx.x;
    float pos = (float)(Sc - 1 - i);
    #pragma unroll
    for (int l = 0; l < 4; l++) {
        int c = threadIdx.x + l * 256;
        int j = (c < Dc/2) ? c : (c - Dc/2);
        float invf = expf(-logf(10000.f) * ((float)(2*j) / (float)Dc));
        float a = pos * invf;
        float v = (c < Dc/2) ? sinf(a) : cosf(a);
        bf16 h, lo; split1(v, h, lo);
        peh[(size_t)i*Dc + c] = h; pel[(size_t)i*Dc + c] = lo;
    }
}

// ---------------- attention operand prep (q-side pre-scaled by 0.125) ----------------
__global__ __launch_bounds__(256)
void qprep(const float* __restrict__ qkv, const float* __restrict__ ub, const float* __restrict__ vb,
           bf16* quh, bf16* qul, bf16* qvh, bf16* qvl, bf16* kh, bf16* kl)
{
    int tok = blockIdx.x;
    int b = tok >> 10, s = tok & 1023;
    #pragma unroll
    for (int l = 0; l < 4; l++) {
        int c = threadIdx.x + l*256;
        int h = c >> 6, d = c & 63;
        size_t src = (size_t)tok*3072 + c;
        float qf = qkv[src], kf = qkv[src + 1024];
        size_t dst = ((size_t)(b*NHc + h)*Sc + s)*64 + d;
        bf16 hh, ll;
        split1((qf + ub[c]) * 0.125f, hh, ll); quh[dst] = hh; qul[dst] = ll;
        split1((qf + vb[c]) * 0.125f, hh, ll); qvh[dst] = hh; qvl[dst] = ll;
        split1(kf, hh, ll);                   kh[dst] = hh;  kl[dst] = ll;
    }
}
__global__ __launch_bounds__(256)
void vtprep(const float* __restrict__ qkv, bf16* vth, bf16* vtl)
{
    __shared__ float t[32][33];
    int tx = threadIdx.x & 31, ty = threadIdx.x >> 5;
    int s0 = blockIdx.x * 32, d0 = blockIdx.y * 32, bh = blockIdx.z;
    int b = bh >> 4, h = bh & 15;
    #pragma unroll
    for (int j = 0; j < 4; j++) {
        int sl = ty + j*8;
        t[sl][tx] = qkv[((size_t)(b*Sc + s0 + sl))*3072 + 2048 + h*64 + d0 + tx];
    }
    __syncthreads();
    #pragma unroll
    for (int j = 0; j < 4; j++) {
        int dl = ty + j*8;
        float v = t[tx][dl];
        bf16 hh, ll; split1(v, hh, ll);
        size_t dst = ((size_t)bh*64 + d0 + dl)*Sc + s0 + tx;
        vth[dst] = hh; vtl[dst] = ll;
    }
}
__global__ __launch_bounds__(256)
void rprep(const float* __restrict__ r, bf16* rh, bf16* rl)
{
    int s = blockIdx.x;
    #pragma unroll
    for (int l = 0; l < 4; l++) {
        int c = threadIdx.x + l*256;
        int h = c >> 6, d = c & 63;
        float v = r[(size_t)s*Dc + c];
        bf16 hh, ll; split1(v, hh, ll);
        size_t dst = ((size_t)h*Sc + s)*64 + d;
        rh[dst] = hh; rl[dst] = ll;
    }
}

// ---------------- HMMA split-bf16 GEMM with cp.async double buffering ----------------
#define STG_BYTES 40960
#define OPD_BYTES 10240
#define TG_SMEM   (2*STG_BYTES)

template<int EPI, int OBF>
__global__ __launch_bounds__(256, 2)
void tgemm(const bf16* __restrict__ Ahi, const bf16* __restrict__ Alo,
           const bf16* __restrict__ Bhi, const bf16* __restrict__ Blo,
           float* __restrict__ C, bf16* __restrict__ Chi, bf16* __restrict__ Clo,
           int M, int N, int K,
           const float* __restrict__ bias, const float* __restrict__ rowScale,
           const int* __restrict__ gatherBase, const int* __restrict__ cntBase,
           size_t eStrideB, int eStrideBias)
{
    extern __shared__ char sm[];

    int e = blockIdx.z;
    const int* gather = gatherBase ? gatherBase + e * Tc : nullptr;
    int limit = cntBase ? cntBase[e] : M;
    int m0 = blockIdx.y * 128;
    if (m0 >= limit) return;
    int n0 = blockIdx.x * 128;
    const bf16* BhiE = Bhi + (size_t)e * eStrideB;
    const bf16* BloE = Blo + (size_t)e * eStrideB;
    const float* biasE = (EPI >= 1) ? bias + (size_t)e * eStrideBias : bias;

    int tid = threadIdx.x, wid = tid >> 5, lane = tid & 31;
    int wm = (wid & 3) * 32, wn = (wid >> 2) * 64;
    uint32_t sbase = smem_u32(sm);

    const bf16 *aph[2], *apl[2], *bph[2], *bpl[2];
    uint32_t soff[2], asz[2];
    #pragma unroll
    for (int l = 0; l < 2; l++) {
        int slot = tid + 256*l;
        int row = slot >> 2, seg = slot & 3;
        soff[l] = (uint32_t)(row * 80 + seg * 16);
        int gr = m0 + row;
        if (gr < limit) {
            int sr = gather ? gather[gr] : gr;
            aph[l] = Ahi + (size_t)sr * K + seg * 8;
            apl[l] = Alo + (size_t)sr * K + seg * 8;
            asz[l] = 16;
        } else {
            aph[l] = Ahi; apl[l] = Alo; asz[l] = 0;
        }
        size_t off = (size_t)(n0 + row) * K + seg * 8;
        bph[l] = BhiE + off; bpl[l] = BloE + off;
    }

    int t4 = lane >> 3;
    int rr = (lane & 7) + (t4 & 1) * 8;
    int cc = (t4 >> 1) * 8;

    float acc[2][8][4];
    #pragma unroll
    for (int i = 0; i < 2; i++)
        #pragma unroll
        for (int j = 0; j < 8; j++)
            #pragma unroll
            for (int q = 0; q < 4; q++) acc[i][j][q] = 0.f;

    int Kc = K >> 5;

    #pragma unroll
    for (int s = 0; s < 2; s++) {
        if (s < Kc) {
            uint32_t b = sbase + s * STG_BYTES;
            int ko = s * 32;
            #pragma unroll
            for (int l = 0; l < 2; l++) {
                CPA16(b + soff[l],               aph[l] + ko, asz[l]);
                CPA16(b + OPD_BYTES + soff[l],   apl[l] + ko, asz[l]);
                CPA16(b + 2*OPD_BYTES + soff[l], bph[l] + ko, 16u);
                CPA16(b + 3*OPD_BYTES + soff[l], bpl[l] + ko, 16u);
            }
            CPC();
        }
    }

    for (int c = 0; c < Kc; c++) {
        if (c + 1 < Kc) { CPW1(); } else { CPW0(); }
        __syncthreads();

        uint32_t sb = sbase + (uint32_t)(c & 1) * STG_BYTES;
        uint32_t baAH = sb, baAL = sb + OPD_BYTES;
        uint32_t baBH = sb + 2*OPD_BYTES, baBL = sb + 3*OPD_BYTES;

        #pragma unroll
        for (int k16 = 0; k16 < 32; k16 += 16) {
            uint32_t aH[2][4], aL[2][4];
            #pragma unroll
            for (int mi = 0; mi < 2; mi++) {
                uint32_t off = ((uint32_t)(wm + mi*16 + rr) * 40u + (uint32_t)(k16 + cc)) * 2u;
                ldm4(aH[mi], baAH + off);
                ldm4(aL[mi], baAL + off);
            }
            uint32_t bH[4][4], bL[4][4];
            #pragma unroll
            for (int ni = 0; ni < 4; ni++) {
                uint32_t off = ((uint32_t)(wn + ni*16 + rr) * 40u + (uint32_t)(k16 + cc)) * 2u;
                ldm4(bH[ni], baBH + off);
                ldm4(bL[ni], baBL + off);
            }
            #pragma unroll
            for (int mi = 0; mi < 2; mi++)
                #pragma unroll
                for (int ni = 0; ni < 4; ni++)
                    #pragma unroll
                    for (int h = 0; h < 2; h++) {
                        int j = ni*2 + h;
                        mma_bf16(acc[mi][j], aH[mi], bH[ni][h], bH[ni][h+2]);
                        mma_bf16(acc[mi][j], aH[mi], bL[ni][h], bL[ni][h+2]);
                        mma_bf16(acc[mi][j], aL[mi], bH[ni][h], bH[ni][h+2]);
                    }
        }
        __syncthreads();

        if (c + 2 < Kc) {
            uint32_t b = sbase + (uint32_t)(c & 1) * STG_BYTES;
            int ko = (c + 2) * 32;
            #pragma unroll
            for (int l = 0; l < 2; l++) {
                CPA16(b + soff[l],               aph[l] + ko, asz[l]);
                CPA16(b + OPD_BYTES + soff[l],   apl[l] + ko, asz[l]);
                CPA16(b + 2*OPD_BYTES + soff[l], bph[l] + ko, 16u);
                CPA16(b + 3*OPD_BYTES + soff[l], bpl[l] + ko, 16u);
            }
            CPC();
        }
    }

    #pragma unroll
    for (int mi = 0; mi < 2; mi++) {
        #pragma unroll
        for (int half = 0; half < 2; half++) {
            int gr = m0 + wm + mi*16 + (lane >> 2) + half*8;
            if (gr >= limit) continue;
            int crow = gather ? gather[gr] : gr;
            float rs = 1.f;
            if (EPI == 3) rs = rowScale[crow];
            #pragma unroll
            for (int j = 0; j < 8; j++) {
                int col = n0 + wn + j*8 + (lane & 3)*2;
                float vx = acc[mi][j][half*2 + 0];
                float vy = acc[mi][j][half*2 + 1];
                if (EPI >= 1) { vx += biasE[col]; vy += biasE[col+1]; }
                if (EPI == 2) { vx = fmaxf(vx, 0.f); vy = fmaxf(vy, 0.f); }
                if (EPI == 3) { vx *= rs; vy *= rs; }
                if (OBF == 0) {
                    *(float2*)(C + (size_t)crow * N + col) = make_float2(vx, vy);
                } else {
                    bf162 h, l; split2(vx, vy, h, l);
                    *(bf162*)(Chi + (size_t)crow * N + col) = h;
                    *(bf162*)(Clo + (size_t)crow * N + col) = l;
                }
            }
        }
    }
}

// ---------------- fused TXL attention (P kept in registers) ----------------
#define FA_QUH 0
#define FA_QUL 9216
#define FA_QVH 18432
#define FA_QVL 27648
#define FA_KH  36864
#define FA_KL  46080
#define FA_RH  55296
#define FA_RL  73728
#define FA_VH  92160
#define FA_VL  101376
#define FA_OS  110592           // fp32 [64][68] cross-warp O partial buffer (17408 B)
#define FA_BD  129024
#define FA_RED (FA_BD + 33792)
#define FA_SMEM (FA_RED + 1024)

__global__ __launch_bounds__(256, 1)
void fattn(const bf16* __restrict__ quh, const bf16* __restrict__ qul,
           const bf16* __restrict__ qvh, const bf16* __restrict__ qvl,
           const bf16* __restrict__ kh,  const bf16* __restrict__ kl,
           const bf16* __restrict__ rhp, const bf16* __restrict__ rlp,
           const bf16* __restrict__ vth, const bf16* __restrict__ vtl,
           bf16* __restrict__ ctxh, bf16* __restrict__ ctxl)
{
    extern __shared__ char sm[];
    int qt = 15 - blockIdx.x;
    int bh = blockIdx.y;
    int b = bh >> 4, h = bh & 15;
    int q0 = qt * 64;
    uint32_t sb = smem_u32(sm);
    int tid = threadIdx.x, wid = tid >> 5, lane = tid & 31;
    int wm = (wid & 3) * 16, wn = (wid >> 2) * 32;
    int wcol = wid >> 2;
    int t4l = lane >> 3;
    int rr = (lane & 7) + (t4l & 1) * 8;
    int cc = (t4l >> 1) * 8;
    int qrow = (lane >> 2);
    int kc0 = (lane & 3) * 2;

    #pragma unroll
    for (int i = 0; i < 2; i++) {
        int slot = tid + 256*i;
        int row = slot >> 3, seg = slot & 7;
        size_t g = ((size_t)bh*Sc + q0 + row)*64 + seg*8;
        *(uint4*)(sm + FA_QUH + row*144 + seg*16) = *(const uint4*)(quh + g);
        *(uint4*)(sm + FA_QUL + row*144 + seg*16) = *(const uint4*)(qul + g);
        *(uint4*)(sm + FA_QVH + row*144 + seg*16) = *(const uint4*)(qvh + g);
        *(uint4*)(sm + FA_QVL + row*144 + seg*16) = *(const uint4*)(qvl + g);
    }

    float mrow[2] = {-1e30f, -1e30f}, lrow[2] = {0.f, 0.f};
    float oacc[8][4];
    #pragma unroll
    for (int j = 0; j < 8; j++)
        #pragma unroll
        for (int q = 0; q < 4; q++) oacc[j][q] = 0.f;

    for (int kt = 0; kt <= qt; kt++) {
        int k0 = kt * 64;
        int t0 = kt - qt + 15;
        __syncthreads();

        #pragma unroll
        for (int i = 0; i < 2; i++) {
            int slot = tid + 256*i;
            int row = slot >> 3, seg = slot & 7;
            size_t gk = ((size_t)bh*Sc + k0 + row)*64 + seg*8;
            *(uint4*)(sm + FA_KH + row*144 + seg*16) = *(const uint4*)(kh + gk);
            *(uint4*)(sm + FA_KL + row*144 + seg*16) = *(const uint4*)(kl + gk);
            size_t gv = ((size_t)bh*64 + row)*Sc + k0 + seg*8;
            *(uint4*)(sm + FA_VH + row*144 + seg*16) = *(const uint4*)(vth + gv);
            *(uint4*)(sm + FA_VL + row*144 + seg*16) = *(const uint4*)(vtl + gv);
        }
        int tfrom = (kt == 0) ? t0 : t0 + 1;
        for (int t = tfrom; t <= t0 + 1 && t <= 15; t++) {
            int hoff = (t & 1) * 64;
            #pragma unroll
            for (int i = 0; i < 2; i++) {
                int slot = tid + 256*i;
                int row = slot >> 3, seg = slot & 7;
                size_t gr = ((size_t)h*Sc + t*64 + row)*64 + seg*8;
                *(uint4*)(sm + FA_RH + (hoff + row)*144 + seg*16) = *(const uint4*)(rhp + gr);
                *(uint4*)(sm + FA_RL + (hoff + row)*144 + seg*16) = *(const uint4*)(rlp + gr);
            }
        }
        __syncthreads();

        // bd MMAs for new j-tiles -> BD ring
        for (int t = tfrom; t <= t0 + 1 && t <= 15; t++) {
            int hoff = (t & 1) * 64;
            float bacc[4][4];
            #pragma unroll
            for (int j = 0; j < 4; j++)
                #pragma unroll
                for (int q = 0; q < 4; q++) bacc[j][q] = 0.f;
            #pragma unroll
            for (int k16 = 0; k16 < 64; k16 += 16) {
                uint32_t aH[4], aL[4];
                uint32_t offA = ((uint32_t)(wm + rr) * 72u + (uint32_t)(k16 + cc)) * 2u;
                ldm4(aH, sb + FA_QVH + offA);
                ldm4(aL, sb + FA_QVL + offA);
                uint32_t bH[2][4], bL[2][4];
                #pragma unroll
                for (int ni = 0; ni < 2; ni++) {
                    uint32_t offB = ((uint32_t)(hoff + wn + ni*16 + rr) * 72u + (uint32_t)(k16 + cc)) * 2u;
                    ldm4(bH[ni], sb + FA_RH + offB);
                    ldm4(bL[ni], sb + FA_RL + offB);
                }
                #pragma unroll
                for (int ni = 0; ni < 2; ni++)
                    #pragma unroll
                    for (int hb = 0; hb < 2; hb++) {
                        int j = ni*2 + hb;
                        mma_bf16(bacc[j], aH, bH[ni][hb], bH[ni][hb+2]);
                        mma_bf16(bacc[j], aH, bL[ni][hb], bL[ni][hb+2]);
                        mma_bf16(bacc[j], aL, bH[ni][hb], bH[ni][hb+2]);
                    }
            }
            #pragma unroll
            for (int half = 0; half < 2; half++) {
                int row = wm + qrow + half*8;
                #pragma unroll
                for (int j = 0; j < 4; j++) {
                    int col = hoff + wn + j*8 + kc0;
                    *(float2*)(sm + FA_BD + row*528 + col*4) =
                        make_float2(bacc[j][half*2], bacc[j][half*2+1]);
                }
            }
        }

        // ac MMAs
        float s[4][4];
        #pragma unroll
        for (int j = 0; j < 4; j++)
            #pragma unroll
            for (int q = 0; q < 4; q++) s[j][q] = 0.f;
        #pragma unroll
        for (int k16 = 0; k16 < 64; k16 += 16) {
            uint32_t aH[4], aL[4];
            uint32_t offA = ((uint32_t)(wm + rr) * 72u + (uint32_t)(k16 + cc)) * 2u;
            ldm4(aH, sb + FA_QUH + offA);
            ldm4(aL, sb + FA_QUL + offA);
            uint32_t bH[2][4], bL[2][4];
            #pragma unroll
            for (int ni = 0; ni < 2; ni++) {
                uint32_t offB = ((uint32_t)(wn + ni*16 + rr) * 72u + (uint32_t)(k16 + cc)) * 2u;
                ldm4(bH[ni], sb + FA_KH + offB);
                ldm4(bL[ni], sb + FA_KL + offB);
            }
            #pragma unroll
            for (int ni = 0; ni < 2; ni++)
                #pragma unroll
                for (int hb = 0; hb < 2; hb++) {
                    int j = ni*2 + hb;
                    mma_bf16(s[j], aH, bH[ni][hb], bH[ni][hb+2]);
                    mma_bf16(s[j], aH, bL[ni][hb], bL[ni][hb+2]);
                    mma_bf16(s[j], aL, bH[ni][hb], bH[ni][hb+2]);
                }
        }
        __syncthreads();   // BD writes visible

        bool diag = (kt == qt);
        int ringbase = (t0 & 1) * 64;
        float mt2[2], sc2[2], rs2[2];

        // phase 1: add bd, mask, per-warp row max -> smem
        #pragma unroll
        for (int half = 0; half < 2; half++) {
            int row = wm + qrow + half*8;
            float mt = -1e30f;
            #pragma unroll
            for (int j = 0; j < 4; j++) {
                #pragma unroll
                for (int c2 = 0; c2 < 2; c2++) {
                    int colk = wn + j*8 + kc0 + c2;
                    int jcol = colk - row + 63;
                    int phys = (ringbase + jcol) & 127;
                    float val = s[j][half*2 + c2] +
                        *(const float*)(sm + FA_BD + row*528 + phys*4);
                    if (diag && colk > row) val = -1e30f;
                    s[j][half*2 + c2] = val;
                    mt = fmaxf(mt, val);
                }
            }
            mt = fmaxf(mt, __shfl_xor_sync(0xFFFFFFFFu, mt, 1));
            mt = fmaxf(mt, __shfl_xor_sync(0xFFFFFFFFu, mt, 2));
            mt2[half] = mt;
            if ((lane & 3) == 0)
                *(float*)(sm + FA_RED + (wcol*64 + row)*4) = mt;
        }
        __syncthreads();

        // phase 2: combined max, exponentiate, partial sums -> smem (P stays in regs)
        #pragma unroll
        for (int half = 0; half < 2; half++) {
            int row = wm + qrow + half*8;
            float other = *(const float*)(sm + FA_RED + ((1-wcol)*64 + row)*4);
            float mnew = fmaxf(mrow[half], fmaxf(mt2[half], other));
            float scale = __expf(mrow[half] - mnew);
            sc2[half] = scale;
            float rs = 0.f;
            #pragma unroll
            for (int j = 0; j < 4; j++) {
                #pragma unroll
                for (int c2 = 0; c2 < 2; c2++) {
                    float p = __expf(s[j][half*2 + c2] - mnew);
                    s[j][half*2 + c2] = p;
                    rs += p;
                }
            }
            rs += __shfl_xor_sync(0xFFFFFFFFu, rs, 1);
            rs += __shfl_xor_sync(0xFFFFFFFFu, rs, 2);
            rs2[half] = rs;
            if ((lane & 3) == 0)
                *(float*)(sm + FA_RED + 512 + (wcol*64 + row)*4) = rs;
            mrow[half] = mnew;
            #pragma unroll
            for (int j = 0; j < 8; j++) {
                oacc[j][half*2 + 0] *= scale;
                oacc[j][half*2 + 1] *= scale;
            }
        }
        __syncthreads();   // row sums visible

        // phase 3: combine row sums
        #pragma unroll
        for (int half = 0; half < 2; half++) {
            int row = wm + qrow + half*8;
            float other = *(const float*)(sm + FA_RED + 512 + ((1-wcol)*64 + row)*4);
            lrow[half] = lrow[half] * sc2[half] + rs2[half] + other;
        }

        // PV MMAs: each warp covers its 32-k slice (P from regs) x all 64 d-cols
        #pragma unroll
        for (int kc = 0; kc < 2; kc++) {
            uint32_t aH[4], aL[4];
            {
                bf162 h0, l0;
                split2(s[2*kc][0],   s[2*kc][1],   h0, l0); aH[0] = *(uint32_t*)&h0; aL[0] = *(uint32_t*)&l0;
                split2(s[2*kc][2],   s[2*kc][3],   h0, l0); aH[1] = *(uint32_t*)&h0; aL[1] = *(uint32_t*)&l0;
                split2(s[2*kc+1][0], s[2*kc+1][1], h0, l0); aH[2] = *(uint32_t*)&h0; aL[2] = *(uint32_t*)&l0;
                split2(s[2*kc+1][2], s[2*kc+1][3], h0, l0); aH[3] = *(uint32_t*)&h0; aL[3] = *(uint32_t*)&l0;
            }
            #pragma unroll
            for (int ni = 0; ni < 4; ni++) {
                uint32_t bH[4], bL[4];
                uint32_t offB = ((uint32_t)(ni*16 + rr) * 72u + (uint32_t)(wn + kc*16 + cc)) * 2u;
                ldm4(bH, sb + FA_VH + offB);
                ldm4(bL, sb + FA_VL + offB);
                #pragma unroll
                for (int hb = 0; hb < 2; hb++) {
                    int j = ni*2 + hb;
                    mma_bf16(oacc[j], aH, bH[hb], bH[hb+2]);
                    mma_bf16(oacc[j], aH, bL[hb], bL[hb+2]);
                    mma_bf16(oacc[j], aL, bH[hb], bH[hb+2]);
                }
            }
        }
    }

    // epilogue: cross-warp partial sum, normalize, store
    if (wcol == 0) {
        #pragma unroll
        for (int half = 0; half < 2; half++) {
            int row = wm + qrow + half*8;
            #pragma unroll
            for (int j = 0; j < 8; j++) {
                *(float2*)(sm + FA_OS + row*272 + (j*8 + kc0)*4) =
                    make_float2(oacc[j][half*2], oacc[j][half*2+1]);
            }
        }
    }
    __syncthreads();
    if (wcol == 1) {
        #pragma unroll
        for (int half = 0; half < 2; half++) {
            int row = wm + qrow + half*8;
            int tok = b*Sc + q0 + row;
            float inv = 1.f / lrow[half];
            #pragma unroll
            for (int j = 0; j < 8; j++) {
                float2 o = *(float2*)(sm + FA_OS + row*272 + (j*8 + kc0)*4);
                float vx = (oacc[j][half*2 + 0] + o.x) * inv;
                float vy = (oacc[j][half*2 + 1] + o.y) * inv;
                int col = h*64 + j*8 + kc0;
                bf162 hh, ll;
                split2(vx, vy, hh, ll);
                *(bf162*)(ctxh + (size_t)tok*Dc + col) = hh;
                *(bf162*)(ctxl + (size_t)tok*Dc + col) = ll;
            }
        }
    }
}

// ---------------- residual + layernorm ----------------
// OBF: 0 = fp32 only, 1 = fp32 + bf16 hi/lo, 2 = bf16 hi/lo only
template<int OBF>
__global__ __launch_bounds__(256)
void rln_k(const float* __restrict__ x, const float* __restrict__ y,
           const float* __restrict__ g, const float* __restrict__ bta,
           float* __restrict__ out, bf16* __restrict__ oh, bf16* __restrict__ ol)
{
    int row = blockIdx.x;
    int tid = threadIdx.x;
    __shared__ float red[256];
    float v[4];
    float s = 0.f, ss = 0.f;
    #pragma unroll
    for (int l = 0; l < 4; l++) {
        size_t idx = (size_t)row*Dc + tid + l*256;
        float val = x[idx] + y[idx];
        v[l] = val; s += val; ss += val*val;
    }
    red[tid] = s; __syncthreads();
    for (int st = 128; st > 0; st >>= 1) { if (tid < st) red[tid] += red[tid+st]; __syncthreads(); }
    float mean = red[0] * (1.f/Dc); __syncthreads();
    red[tid] = ss; __syncthreads();
    for (int st = 128; st > 0; st >>= 1) { if (tid < st) red[tid] += red[tid+st]; __syncthreads(); }
    float var = red[0] * (1.f/Dc) - mean*mean;
    float inv = rsqrtf(var + 1e-5f);
    #pragma unroll
    for (int l = 0; l < 4; l++) {
        int c = tid + l*256;
        float o = (v[l] - mean) * inv * g[c] + bta[c];
        if (OBF != 2) out[(size_t)row*Dc + c] = o;
        if (OBF >= 1) {
            bf16 hh, ll; split1(o, hh, ll);
            oh[(size_t)row*Dc + c] = hh;
            ol[(size_t)row*Dc + c] = ll;
        }
    }
}

// ---------------- router ----------------
__global__ void zero_cnt(int* cnt) { if (threadIdx.x < NEc) cnt[threadIdx.x] = 0; }

__global__ __launch_bounds__(256)
void router_k(const float* __restrict__ h2, const float* __restrict__ Wg,
              float* __restrict__ gate, int* __restrict__ cnt, int* __restrict__ idxlist)
{
    int warp = (blockIdx.x * blockDim.x + threadIdx.x) >> 5;
    int lane = threadIdx.x & 31;
    if (warp >= Tc) return;
    const float* hrow = h2 + (size_t)warp * Dc;
    float logit[NEc];
    #pragma unroll
    for (int e = 0; e < NEc; e++) {
        float p = 0.f;
        for (int d = lane; d < Dc; d += 32) p += hrow[d] * Wg[d*NEc + e];
        #pragma unroll
        for (int off = 16; off > 0; off >>= 1) p += __shfl_xor_sync(0xFFFFFFFFu, p, off);
        logit[e] = p;
    }
    float m = logit[0]; int am = 0;
    #pragma unroll
    for (int e = 1; e < NEc; e++) if (logit[e] > m) { m = logit[e]; am = e; }
    float sum = 0.f;
    #pragma unroll
    for (int e = 0; e < NEc; e++) sum += expf(logit[e] - m);
    if (lane == 0) {
        gate[warp] = 1.f / sum;
        int pos = atomicAdd(&cnt[am], 1);
        idxlist[am*Tc + pos] = warp;
    }
}

// ---------------- launch ----------------
extern "C" void kernel_launch(void* const* d_in, const int* in_sizes, int n_in,
                              void* d_out, int out_size)
{
    const float* x    = (const float*)d_in[0];
    const float* Wqkv = (const float*)d_in[1];
    const float* Wo   = (const float*)d_in[2];
    const float* Wr   = (const float*)d_in[3];
    const float* u_b  = (const float*)d_in[4];
    const float* v_b  = (const float*)d_in[5];
    const float* ln1g = (const float*)d_in[6];
    const float* ln1b = (const float*)d_in[7];
    const float* Wff1 = (const float*)d_in[8];
    const float* bff1 = (const float*)d_in[9];
    const float* Wff2 = (const float*)d_in[10];
    const float* bff2 = (const float*)d_in[11];
    const float* ln2g = (const float*)d_in[12];
    const float* ln2b = (const float*)d_in[13];
    const float* Wg   = (const float*)d_in[14];
    const float* We1  = (const float*)d_in[15];
    const float* be1  = (const float*)d_in[16];
    const float* We2  = (const float*)d_in[17];
    const float* be2  = (const float*)d_in[18];
    const float* ln3g = (const float*)d_in[19];
    const float* ln3b = (const float*)d_in[20];
    const float* Wout = (const float*)d_in[21];
    float* out = (float*)d_out;

    static int inited = 0;
    if (!inited) {
        cudaFuncSetAttribute(tgemm<0,0>, cudaFuncAttributeMaxDynamicSharedMemorySize, TG_SMEM);
        cudaFuncSetAttribute(tgemm<1,0>, cudaFuncAttributeMaxDynamicSharedMemorySize, TG_SMEM);
        cudaFuncSetAttribute(tgemm<2,1>, cudaFuncAttributeMaxDynamicSharedMemorySize, TG_SMEM);
        cudaFuncSetAttribute(tgemm<3,0>, cudaFuncAttributeMaxDynamicSharedMemorySize, TG_SMEM);
        cudaFuncSetAttribute(fattn,      cudaFuncAttributeMaxDynamicSharedMemorySize, FA_SMEM);
        inited = 1;
    }

    float *qkv, *r, *ao, *ff, *h1, *h2, *moe, *gate;
    int *cnt, *idx;
    bf16 *whi, *wlo, *peh, *pel, *xh, *xl;
    bf16 *quh, *qul, *qvh, *qvl, *kh, *kl, *vth, *vtl, *rh, *rl;
    bf16 *ctxh, *ctxl, *h1h, *h1l, *h2h, *h2l, *h3h, *h3l, *ffhh, *ffhl;

    cudaGetSymbolAddress((void**)&qkv, g_qkv);
    cudaGetSymbolAddress((void**)&r,   g_r);
    cudaGetSymbolAddress((void**)&ao,  g_ao);
    cudaGetSymbolAddress((void**)&ff,  g_ff);
    cudaGetSymbolAddress((void**)&h1,  g_h1);
    cudaGetSymbolAddress((void**)&h2,  g_h2);
    cudaGetSymbolAddress((void**)&moe, g_moe);
    cudaGetSymbolAddress((void**)&gate,g_gate);
    cudaGetSymbolAddress((void**)&cnt, g_cnt);
    cudaGetSymbolAddress((void**)&idx, g_idx);
    cudaGetSymbolAddress((void**)&whi, g_whi);
    cudaGetSymbolAddress((void**)&wlo, g_wlo);
    cudaGetSymbolAddress((void**)&peh, g_peh);
    cudaGetSymbolAddress((void**)&pel, g_pel);
    cudaGetSymbolAddress((void**)&xh,  g_xh);
    cudaGetSymbolAddress((void**)&xl,  g_xl);
    cudaGetSymbolAddress((void**)&quh, g_quh);
    cudaGetSymbolAddress((void**)&qul, g_qul);
    cudaGetSymbolAddress((void**)&qvh, g_qvh);
    cudaGetSymbolAddress((void**)&qvl, g_qvl);
    cudaGetSymbolAddress((void**)&kh,  g_kh);
    cudaGetSymbolAddress((void**)&kl,  g_kl);
    cudaGetSymbolAddress((void**)&vth, g_vth);
    cudaGetSymbolAddress((void**)&vtl, g_vtl);
    cudaGetSymbolAddress((void**)&rh,  g_rh);
    cudaGetSymbolAddress((void**)&rl,  g_rl);
    cudaGetSymbolAddress((void**)&ctxh,g_ctxh);
    cudaGetSymbolAddress((void**)&ctxl,g_ctxl);
    cudaGetSymbolAddress((void**)&h1h, g_h1h);
    cudaGetSymbolAddress((void**)&h1l, g_h1l);
    cudaGetSymbolAddress((void**)&h2h, g_h2h);
    cudaGetSymbolAddress((void**)&h2l, g_h2l);
    cudaGetSymbolAddress((void**)&h3h, g_h3h);
    cudaGetSymbolAddress((void**)&h3l, g_h3l);
    cudaGetSymbolAddress((void**)&ffhh,g_ffhh);
    cudaGetSymbolAddress((void**)&ffhl,g_ffhl);

    // weight transpose + split
    wconv<<<dim3(3072/64, 1024/64), 256>>>(Wqkv, whi+OFF_QKV,  wlo+OFF_QKV,  1024, 3072);
    wconv<<<dim3(1024/64, 1024/64), 256>>>(Wr,   whi+OFF_WR,   wlo+OFF_WR,   1024, 1024);
    wconv<<<dim3(1024/64, 1024/64), 256>>>(Wo,   whi+OFF_WO,   wlo+OFF_WO,   1024, 1024);
    wconv<<<dim3(4096/64, 1024/64), 256>>>(Wff1, whi+OFF_FF1,  wlo+OFF_FF1,  1024, 4096);
    wconv<<<dim3(1024/64, 4096/64), 256>>>(Wff2, whi+OFF_FF2,  wlo+OFF_FF2,  4096, 1024);
    wconv<<<dim3(1024/64, 1024/64), 256>>>(Wout, whi+OFF_WOUT, wlo+OFF_WOUT, 1024, 1024);
    wconv<<<dim3(4096/64, 1024/64, NEc), 256>>>(We1, whi+OFF_WE1, wlo+OFF_WE1, 1024, 4096);
    wconv<<<dim3(1024/64, 4096/64, NEc), 256>>>(We2, whi+OFF_WE2, wlo+OFF_WE2, 4096, 1024);

    pe_kernel<<<Sc, 256>>>(peh, pel);
    econv<<<Tc, 256>>>(x, xh, xl);

    // projections
    tgemm<0,0><<<dim3(3072/128, Tc/128), 256, TG_SMEM>>>(xh, xl, whi+OFF_QKV, wlo+OFF_QKV,
        qkv, nullptr, nullptr, Tc, 3072, 1024, nullptr, nullptr, nullptr, nullptr, 0, 0);
    tgemm<0,0><<<dim3(1024/128, Sc/128), 256, TG_SMEM>>>(peh, pel, whi+OFF_WR, wlo+OFF_WR,
        r, nullptr, nullptr, Sc, 1024, 1024, nullptr, nullptr, nullptr, nullptr, 0, 0);

    // attention prep
    qprep<<<Tc, 256>>>(qkv, u_b, v_b, quh, qul, qvh, qvl, kh, kl);
    vtprep<<<dim3(Sc/32, 2, BHc), 256>>>(qkv, vth, vtl);
    rprep<<<Sc, 256>>>(r, rh, rl);

    // fused attention
    fattn<<<dim3(16, BHc), 256, FA_SMEM>>>(quh, qul, qvh, qvl, kh, kl, rh, rl,
                                           vth, vtl, ctxh, ctxl);
    tgemm<0,0><<<dim3(1024/128, Tc/128), 256, TG_SMEM>>>(ctxh, ctxl, whi+OFF_WO, wlo+OFF_WO,
        ao, nullptr, nullptr, Tc, 1024, 1024, nullptr, nullptr, nullptr, nullptr, 0, 0);
    rln_k<1><<<Tc, 256>>>(x, ao, ln1g, ln1b, h1, h1h, h1l);

    // FFN
    tgemm<2,1><<<dim3(4096/128, Tc/128), 256, TG_SMEM>>>(h1h, h1l, whi+OFF_FF1, wlo+OFF_FF1,
        nullptr, ffhh, ffhl, Tc, 4096, 1024, bff1, nullptr, nullptr, nullptr, 0, 0);
    tgemm<1,0><<<dim3(1024/128, Tc/128), 256, TG_SMEM>>>(ffhh, ffhl, whi+OFF_FF2, wlo+OFF_FF2,
        ff, nullptr, nullptr, Tc, 1024, 4096, bff2, nullptr, nullptr, nullptr, 0, 0);
    rln_k<1><<<Tc, 256>>>(h1, ff, ln2g, ln2b, h2, h2h, h2l);

    // MoE
    zero_cnt<<<1, 32>>>(cnt);
    router_k<<<Tc/8, 256>>>(h2, Wg, gate, cnt, idx);
    tgemm<2,1><<<dim3(4096/128, Tc/128, NEc), 256, TG_SMEM>>>(
        h2h, h2l, whi+OFF_WE1, wlo+OFF_WE1,
        nullptr, ffhh, ffhl, Tc, 4096, 1024, be1, nullptr, idx, cnt,
        (size_t)FFc*Dc, FFc);
    tgemm<3,0><<<dim3(1024/128, Tc/128, NEc), 256, TG_SMEM>>>(
        ffhh, ffhl, whi+OFF_WE2, wlo+OFF_WE2,
        moe, nullptr, nullptr, Tc, 1024, 4096, be2, gate, idx, cnt,
        (size_t)Dc*FFc, Dc);
    rln_k<2><<<Tc, 256>>>(h2, moe, ln3g, ln3b, nullptr, h3h, h3l);

    // output projection
    tgemm<0,0><<<dim3(1024/128, Tc/128), 256, TG_SMEM>>>(h3h, h3l, whi+OFF_WOUT, wlo+OFF_WOUT,
        out, nullptr, nullptr, Tc, 1024, 1024, nullptr, nullptr, nullptr, nullptr, 0, 0);
}

// round 17
// speedup vs baseline: 1.0938x; 1.0211x over previous
#include <cuda_runtime.h>
#include <cuda_bf16.h>
#include <math.h>
#include <stdint.h>

#define Bc 4
#define Sc 1024
#define Dc 1024
#define NHc 16
#define DHc 64
#define FFc 4096
#define NEc 8
#define Tc (Bc*Sc)
#define BHc (Bc*NHc)

typedef __nv_bfloat16 bf16;
typedef __nv_bfloat162 bf162;

// ---------------- fp32 scratch ----------------
__device__ float g_qkv[(size_t)Tc*3*Dc];
__device__ float g_r[Sc*Dc];
__device__ float g_ao[(size_t)Tc*Dc];
__device__ float g_ff[(size_t)Tc*Dc];
__device__ float g_h1[(size_t)Tc*Dc];
__device__ float g_h2[(size_t)Tc*Dc];
__device__ float g_moe[(size_t)Tc*Dc];
__device__ float g_gate[Tc];
__device__ int   g_cnt[NEc];
__device__ int   g_idx[NEc*Tc];

// ---------------- bf16 hi/lo scratch ----------------
__device__ bf16 g_peh[Sc*Dc],  g_pel[Sc*Dc];
__device__ bf16 g_xh[(size_t)Tc*Dc],  g_xl[(size_t)Tc*Dc];
__device__ bf16 g_quh[(size_t)Tc*Dc], g_qul[(size_t)Tc*Dc];
__device__ bf16 g_qvh[(size_t)Tc*Dc], g_qvl[(size_t)Tc*Dc];
__device__ bf16 g_kh[(size_t)Tc*Dc],  g_kl[(size_t)Tc*Dc];
__device__ bf16 g_vth[(size_t)Tc*Dc], g_vtl[(size_t)Tc*Dc];
__device__ bf16 g_rh[NHc*Sc*DHc],     g_rl[NHc*Sc*DHc];
__device__ bf16 g_ctxh[(size_t)Tc*Dc], g_ctxl[(size_t)Tc*Dc];
__device__ bf16 g_h1h[(size_t)Tc*Dc], g_h1l[(size_t)Tc*Dc];
__device__ bf16 g_h2h[(size_t)Tc*Dc], g_h2l[(size_t)Tc*Dc];
__device__ bf16 g_h3h[(size_t)Tc*Dc], g_h3l[(size_t)Tc*Dc];
__device__ bf16 g_ffhh[(size_t)Tc*FFc], g_ffhl[(size_t)Tc*FFc];

// transposed split-bf16 weights: [N,K] layout, hi + lo
#define OFF_QKV  0
#define OFF_WR   3145728
#define OFF_WO   4194304
#define OFF_FF1  5242880
#define OFF_FF2  9437184
#define OFF_WE1  13631488
#define OFF_WE2  47185920
#define OFF_WOUT 80740352
#define WTOT     81788928
__device__ bf16 g_whi[WTOT];
__device__ bf16 g_wlo[WTOT];

// ---------------- helpers ----------------
__device__ __forceinline__ uint32_t smem_u32(const void* p) {
    uint32_t a;
    asm("{ .reg .u64 t; cvta.to.shared.u64 t, %1; cvt.u32.u64 %0, t; }" : "=r"(a) : "l"(p));
    return a;
}
__device__ __forceinline__ void ldm4(uint32_t* r, uint32_t a) {
    asm volatile("ldmatrix.sync.aligned.m8n8.x4.shared.b16 {%0,%1,%2,%3}, [%4];"
        : "=r"(r[0]), "=r"(r[1]), "=r"(r[2]), "=r"(r[3]) : "r"(a));
}
__device__ __forceinline__ void mma_bf16(float* c, const uint32_t* a, uint32_t b0, uint32_t b1) {
    asm volatile("mma.sync.aligned.m16n8k16.row.col.f32.bf16.bf16.f32 "
        "{%0,%1,%2,%3}, {%4,%5,%6,%7}, {%8,%9}, {%0,%1,%2,%3};"
        : "+f"(c[0]), "+f"(c[1]), "+f"(c[2]), "+f"(c[3])
        : "r"(a[0]), "r"(a[1]), "r"(a[2]), "r"(a[3]), "r"(b0), "r"(b1));
}
__device__ __forceinline__ void split1(float v, bf16& h, bf16& l) {
    h = __float2bfloat16_rn(v);
    l = __float2bfloat16_rn(v - __bfloat162float(h));
}
__device__ __forceinline__ void split2(float x, float y, bf162& h, bf162& l) {
    h = __floats2bfloat162_rn(x, y);
    float2 hf = __bfloat1622float2(h);
    l = __floats2bfloat162_rn(x - hf.x, y - hf.y);
}
#define CPA16(dst, src, sz) \
    asm volatile("cp.async.cg.shared.global [%0], [%1], 16, %2;" :: "r"(dst), "l"(src), "r"(sz))
#define CPC()  asm volatile("cp.async.commit_group;" ::: "memory")
#define CPW1() asm volatile("cp.async.wait_group 1;" ::: "memory")
#define CPW0() asm volatile("cp.async.wait_group 0;" ::: "memory")

// ---------------- weight transpose + split: W[K,N] -> hi/lo [N,K] ----------------
// float4 batched loads (high MLP), component-rotated STS (2-way conflicts).
__global__ __launch_bounds__(256)
void wconv(const float* __restrict__ W, bf16* __restrict__ hi,
           bf16* __restrict__ lo, int K, int N)
{
    __shared__ float t[64][68];
    int tid = threadIdx.x;
    int nb = blockIdx.x * 64, kb = blockIdx.y * 64;
    size_t eoff = (size_t)blockIdx.z * K * N;

    int seg = tid & 15;        // 4-col group in n
    int i0  = tid >> 4;        // k row base (0..15)
    float4 v[4];
    #pragma unroll
    for (int p = 0; p < 4; p++) {
        int i = i0 + p * 16;
        v[p] = *(const float4*)(W + eoff + (size_t)(kb + i) * N + nb + seg * 4);
    }
    #pragma unroll
    for (int p = 0; p < 4; p++) {
        int i = i0 + p * 16;
        #pragma unroll
        for (int c = 0; c < 4; c++) {
            int cr = (c + seg) & 3;
            float val = (cr == 0) ? v[p].x : (cr == 1) ? v[p].y :
                        (cr == 2) ? v[p].z : v[p].w;
            t[seg * 4 + cr][i] = val;
        }
    }
    __syncthreads();

    int kseg = tid & 15;
    int n0t  = tid >> 4;
    #pragma unroll
    for (int l = 0; l < 4; l++) {
        int n = n0t + l * 16;
        float4 vv = *(float4*)&t[n][kseg * 4];
        bf162 h0, l0, h1, l1;
        split2(vv.x, vv.y, h0, l0);
        split2(vv.z, vv.w, h1, l1);
        size_t dst = eoff + (size_t)(nb + n) * K + kb + kseg * 4;
        *(uint2*)(hi + dst) = make_uint2(*(uint32_t*)&h0, *(uint32_t*)&h1);
        *(uint2*)(lo + dst) = make_uint2(*(uint32_t*)&l0, *(uint32_t*)&l1);
    }
}

// ---------------- elementwise fp32 -> bf16 hi/lo ----------------
__global__ __launch_bounds__(256)
void econv(const float* __restrict__ src, bf16* __restrict__ hi, bf16* __restrict__ lo)
{
    size_t i = (size_t)blockIdx.x * 1024 + threadIdx.x;
    #pragma unroll
    for (int l = 0; l < 4; l++) {
        float v = src[i + l*256];
        bf16 h, lo_;
        split1(v, h, lo_);
        hi[i + l*256] = h; lo[i + l*256] = lo_;
    }
}

// ---------------- positional embedding (bf16 hi/lo) ----------------
__global__ void pe_kernel(bf16* __restrict__ peh, bf16* __restrict__ pel) {
    int i = blockIdx.x;
    float pos = (float)(Sc - 1 - i);
    #pragma unroll
    for (int l = 0; l < 4; l++) {
        int c = threadIdx.x + l * 256;
        int j = (c < Dc/2) ? c : (c - Dc/2);
        float invf = expf(-logf(10000.f) * ((float)(2*j) / (float)Dc));
        float a = pos * invf;
        float v = (c < Dc/2) ? sinf(a) : cosf(a);
        bf16 h, lo; split1(v, h, lo);
        peh[(size_t)i*Dc + c] = h; pel[(size_t)i*Dc + c] = lo;
    }
}

// ---------------- attention operand prep (q-side pre-scaled by 0.125) ----------------
__global__ __launch_bounds__(256)
void qprep(const float* __restrict__ qkv, const float* __restrict__ ub, const float* __restrict__ vb,
           bf16* quh, bf16* qul, bf16* qvh, bf16* qvl, bf16* kh, bf16* kl)
{
    int tok = blockIdx.x;
    int b = tok >> 10, s = tok & 1023;
    #pragma unroll
    for (int l = 0; l < 4; l++) {
        int c = threadIdx.x + l*256;
        int h = c >> 6, d = c & 63;
        size_t src = (size_t)tok*3072 + c;
        float qf = qkv[src], kf = qkv[src + 1024];
        size_t dst = ((size_t)(b*NHc + h)*Sc + s)*64 + d;
        bf16 hh, ll;
        split1((qf + ub[c]) * 0.125f, hh, ll); quh[dst] = hh; qul[dst] = ll;
        split1((qf + vb[c]) * 0.125f, hh, ll); qvh[dst] = hh; qvl[dst] = ll;
        split1(kf, hh, ll);                   kh[dst] = hh;  kl[dst] = ll;
    }
}
__global__ __launch_bounds__(256)
void vtprep(const float* __restrict__ qkv, bf16* vth, bf16* vtl)
{
    __shared__ float t[32][33];
    int tx = threadIdx.x & 31, ty = threadIdx.x >> 5;
    int s0 = blockIdx.x * 32, d0 = blockIdx.y * 32, bh = blockIdx.z;
    int b = bh >> 4, h = bh & 15;
    #pragma unroll
    for (int j = 0; j < 4; j++) {
        int sl = ty + j*8;
        t[sl][tx] = qkv[((size_t)(b*Sc + s0 + sl))*3072 + 2048 + h*64 + d0 + tx];
    }
    __syncthreads();
    #pragma unroll
    for (int j = 0; j < 4; j++) {
        int dl = ty + j*8;
        float v = t[tx][dl];
        bf16 hh, ll; split1(v, hh, ll);
        size_t dst = ((size_t)bh*64 + d0 + dl)*Sc + s0 + tx;
        vth[dst] = hh; vtl[dst] = ll;
    }
}
__global__ __launch_bounds__(256)
void rprep(const float* __restrict__ r, bf16* rh, bf16* rl)
{
    int s = blockIdx.x;
    #pragma unroll
    for (int l = 0; l < 4; l++) {
        int c = threadIdx.x + l*256;
        int h = c >> 6, d = c & 63;
        float v = r[(size_t)s*Dc + c];
        bf16 hh, ll; split1(v, hh, ll);
        size_t dst = ((size_t)h*Sc + s)*64 + d;
        rh[dst] = hh; rl[dst] = ll;
    }
}

// ---------------- HMMA split-bf16 GEMM with cp.async double buffering ----------------
#define STG_BYTES 40960
#define OPD_BYTES 10240
#define TG_SMEM   (2*STG_BYTES)

template<int EPI, int OBF>
__global__ __launch_bounds__(256, 2)
void tgemm(const bf16* __restrict__ Ahi, const bf16* __restrict__ Alo,
           const bf16* __restrict__ Bhi, const bf16* __restrict__ Blo,
           float* __restrict__ C, bf16* __restrict__ Chi, bf16* __restrict__ Clo,
           int M, int N, int K,
           const float* __restrict__ bias, const float* __restrict__ rowScale,
           const int* __restrict__ gatherBase, const int* __restrict__ cntBase,
           size_t eStrideB, int eStrideBias)
{
    extern __shared__ char sm[];

    int e = blockIdx.z;
    const int* gather = gatherBase ? gatherBase + e * Tc : nullptr;
    int limit = cntBase ? cntBase[e] : M;
    int m0 = blockIdx.y * 128;
    if (m0 >= limit) return;
    int n0 = blockIdx.x * 128;
    const bf16* BhiE = Bhi + (size_t)e * eStrideB;
    const bf16* BloE = Blo + (size_t)e * eStrideB;
    const float* biasE = (EPI >= 1) ? bias + (size_t)e * eStrideBias : bias;

    int tid = threadIdx.x, wid = tid >> 5, lane = tid & 31;
    int wm = (wid & 3) * 32, wn = (wid >> 2) * 64;
    uint32_t sbase = smem_u32(sm);

    const bf16 *aph[2], *apl[2], *bph[2], *bpl[2];
    uint32_t soff[2], asz[2];
    #pragma unroll
    for (int l = 0; l < 2; l++) {
        int slot = tid + 256*l;
        int row = slot >> 2, seg = slot & 3;
        soff[l] = (uint32_t)(row * 80 + seg * 16);
        int gr = m0 + row;
        if (gr < limit) {
            int sr = gather ? gather[gr] : gr;
            aph[l] = Ahi + (size_t)sr * K + seg * 8;
            apl[l] = Alo + (size_t)sr * K + seg * 8;
            asz[l] = 16;
        } else {
            aph[l] = Ahi; apl[l] = Alo; asz[l] = 0;
        }
        size_t off = (size_t)(n0 + row) * K + seg * 8;
        bph[l] = BhiE + off; bpl[l] = BloE + off;
    }

    int t4 = lane >> 3;
    int rr = (lane & 7) + (t4 & 1) * 8;
    int cc = (t4 >> 1) * 8;

    float acc[2][8][4];
    #pragma unroll
    for (int i = 0; i < 2; i++)
        #pragma unroll
        for (int j = 0; j < 8; j++)
            #pragma unroll
            for (int q = 0; q < 4; q++) acc[i][j][q] = 0.f;

    int Kc = K >> 5;

    #pragma unroll
    for (int s = 0; s < 2; s++) {
        if (s < Kc) {
            uint32_t b = sbase + s * STG_BYTES;
            int ko = s * 32;
            #pragma unroll
            for (int l = 0; l < 2; l++) {
                CPA16(b + soff[l],               aph[l] + ko, asz[l]);
                CPA16(b + OPD_BYTES + soff[l],   apl[l] + ko, asz[l]);
                CPA16(b + 2*OPD_BYTES + soff[l], bph[l] + ko, 16u);
                CPA16(b + 3*OPD_BYTES + soff[l], bpl[l] + ko, 16u);
            }
            CPC();
        }
    }

    for (int c = 0; c < Kc; c++) {
        if (c + 1 < Kc) { CPW1(); } else { CPW0(); }
        __syncthreads();

        uint32_t sb = sbase + (uint32_t)(c & 1) * STG_BYTES;
        uint32_t baAH = sb, baAL = sb + OPD_BYTES;
        uint32_t baBH = sb + 2*OPD_BYTES, baBL = sb + 3*OPD_BYTES;

        #pragma unroll
        for (int k16 = 0; k16 < 32; k16 += 16) {
            uint32_t aH[2][4], aL[2][4];
            #pragma unroll
            for (int mi = 0; mi < 2; mi++) {
                uint32_t off = ((uint32_t)(wm + mi*16 + rr) * 40u + (uint32_t)(k16 + cc)) * 2u;
                ldm4(aH[mi], baAH + off);
                ldm4(aL[mi], baAL + off);
            }
            uint32_t bH[4][4], bL[4][4];
            #pragma unroll
            for (int ni = 0; ni < 4; ni++) {
                uint32_t off = ((uint32_t)(wn + ni*16 + rr) * 40u + (uint32_t)(k16 + cc)) * 2u;
                ldm4(bH[ni], baBH + off);
                ldm4(bL[ni], baBL + off);
            }
            #pragma unroll
            for (int mi = 0; mi < 2; mi++)
                #pragma unroll
                for (int ni = 0; ni < 4; ni++)
                    #pragma unroll
                    for (int h = 0; h < 2; h++) {
                        int j = ni*2 + h;
                        mma_bf16(acc[mi][j], aH[mi], bH[ni][h], bH[ni][h+2]);
                        mma_bf16(acc[mi][j], aH[mi], bL[ni][h], bL[ni][h+2]);
                        mma_bf16(acc[mi][j], aL[mi], bH[ni][h], bH[ni][h+2]);
                    }
        }
        __syncthreads();

        if (c + 2 < Kc) {
            uint32_t b = sbase + (uint32_t)(c & 1) * STG_BYTES;
            int ko = (c + 2) * 32;
            #pragma unroll
            for (int l = 0; l < 2; l++) {
                CPA16(b + soff[l],               aph[l] + ko, asz[l]);
                CPA16(b + OPD_BYTES + soff[l],   apl[l] + ko, asz[l]);
                CPA16(b + 2*OPD_BYTES + soff[l], bph[l] + ko, 16u);
                CPA16(b + 3*OPD_BYTES + soff[l], bpl[l] + ko, 16u);
            }
            CPC();
        }
    }

    #pragma unroll
    for (int mi = 0; mi < 2; mi++) {
        #pragma unroll
        for (int half = 0; half < 2; half++) {
            int gr = m0 + wm + mi*16 + (lane >> 2) + half*8;
            if (gr >= limit) continue;
            int crow = gather ? gather[gr] : gr;
            float rs = 1.f;
            if (EPI == 3) rs = rowScale[crow];
            #pragma unroll
            for (int j = 0; j < 8; j++) {
                int col = n0 + wn + j*8 + (lane & 3)*2;
                float vx = acc[mi][j][half*2 + 0];
                float vy = acc[mi][j][half*2 + 1];
                if (EPI >= 1) { vx += biasE[col]; vy += biasE[col+1]; }
                if (EPI == 2) { vx = fmaxf(vx, 0.f); vy = fmaxf(vy, 0.f); }
                if (EPI == 3) { vx *= rs; vy *= rs; }
                if (OBF == 0) {
                    *(float2*)(C + (size_t)crow * N + col) = make_float2(vx, vy);
                } else {
                    bf162 h, l; split2(vx, vy, h, l);
                    *(bf162*)(Chi + (size_t)crow * N + col) = h;
                    *(bf162*)(Clo + (size_t)crow * N + col) = l;
                }
            }
        }
    }
}

// ---------------- fused TXL attention (108.5KB smem, 2 CTAs/SM, P in regs) ----------------
#define FA_QUH 0
#define FA_QUL 9216
#define FA_QVH 18432
#define FA_QVL 27648
#define FA_KH  36864            // K tile, reused for V after softmax phase 1
#define FA_KL  46080
#define FA_RH  55296            // single 64-row R tile
#define FA_RL  64512
#define FA_BD  73728            // fp32 [64][132], 33792 B
#define FA_OS  73728            // epilogue O-exchange, aliases BD
#define FA_RED 107520           // [0,512) row max, [512,1024) row sum
#define FA_SMEM 108544

__global__ __launch_bounds__(256, 2)
void fattn(const bf16* __restrict__ quh, const bf16* __restrict__ qul,
           const bf16* __restrict__ qvh, const bf16* __restrict__ qvl,
           const bf16* __restrict__ kh,  const bf16* __restrict__ kl,
           const bf16* __restrict__ rhp, const bf16* __restrict__ rlp,
           const bf16* __restrict__ vth, const bf16* __restrict__ vtl,
           bf16* __restrict__ ctxh, bf16* __restrict__ ctxl)
{
    extern __shared__ char sm[];
    int qt = 15 - blockIdx.x;
    int bh = blockIdx.y;
    int b = bh >> 4, h = bh & 15;
    int q0 = qt * 64;
    uint32_t sb = smem_u32(sm);
    int tid = threadIdx.x, wid = tid >> 5, lane = tid & 31;
    int wm = (wid & 3) * 16, wn = (wid >> 2) * 32;
    int wcol = wid >> 2;
    int t4l = lane >> 3;
    int rr = (lane & 7) + (t4l & 1) * 8;
    int cc = (t4l >> 1) * 8;
    int qrow = (lane >> 2);
    int kc0 = (lane & 3) * 2;

    #pragma unroll
    for (int i = 0; i < 2; i++) {
        int slot = tid + 256*i;
        int row = slot >> 3, seg = slot & 7;
        size_t g = ((size_t)bh*Sc + q0 + row)*64 + seg*8;
        *(uint4*)(sm + FA_QUH + row*144 + seg*16) = *(const uint4*)(quh + g);
        *(uint4*)(sm + FA_QUL + row*144 + seg*16) = *(const uint4*)(qul + g);
        *(uint4*)(sm + FA_QVH + row*144 + seg*16) = *(const uint4*)(qvh + g);
        *(uint4*)(sm + FA_QVL + row*144 + seg*16) = *(const uint4*)(qvl + g);
    }

    float mrow[2] = {-1e30f, -1e30f}, lrow[2] = {0.f, 0.f};
    float oacc[8][4];
    #pragma unroll
    for (int j = 0; j < 8; j++)
        #pragma unroll
        for (int q = 0; q < 4; q++) oacc[j][q] = 0.f;

    for (int kt = 0; kt <= qt; kt++) {
        int k0 = kt * 64;
        int t0 = kt - qt + 15;
        int tnew = t0 + 1;
        __syncthreads();   // prev PV done with V(K buf); Q visible on first iter

        // K tile
        #pragma unroll
        for (int i = 0; i < 2; i++) {
            int slot = tid + 256*i;
            int row = slot >> 3, seg = slot & 7;
            size_t gk = ((size_t)bh*Sc + k0 + row)*64 + seg*8;
            *(uint4*)(sm + FA_KH + row*144 + seg*16) = *(const uint4*)(kh + gk);
            *(uint4*)(sm + FA_KL + row*144 + seg*16) = *(const uint4*)(kl + gk);
        }

        // R tiles (single buffer) + bd MMAs into BD ring
        #pragma unroll 1
        for (int pass = 0; pass < 2; pass++) {
            int t = (pass == 0) ? ((kt == 0) ? t0 : tnew) : tnew;
            bool doIt = (t <= 15) && !(pass == 1 && kt != 0) && !(pass == 1 && tnew > 15);
            if (pass == 1 && kt == 0 && tnew <= 15) doIt = true;
            else if (pass == 1) doIt = false;
            if (doIt) {
                #pragma unroll
                for (int i = 0; i < 2; i++) {
                    int slot = tid + 256*i;
                    int row = slot >> 3, seg = slot & 7;
                    size_t gr = ((size_t)h*Sc + t*64 + row)*64 + seg*8;
                    *(uint4*)(sm + FA_RH + row*144 + seg*16) = *(const uint4*)(rhp + gr);
                    *(uint4*)(sm + FA_RL + row*144 + seg*16) = *(const uint4*)(rlp + gr);
                }
            }
            __syncthreads();   // R (and K on pass 0) visible
            if (doIt) {
                int hoff = (t & 1) * 64;
                float bacc[4][4];
                #pragma unroll
                for (int j = 0; j < 4; j++)
                    #pragma unroll
                    for (int q = 0; q < 4; q++) bacc[j][q] = 0.f;
                #pragma unroll
                for (int k16 = 0; k16 < 64; k16 += 16) {
                    uint32_t aH[4], aL[4];
                    uint32_t offA = ((uint32_t)(wm + rr) * 72u + (uint32_t)(k16 + cc)) * 2u;
                    ldm4(aH, sb + FA_QVH + offA);
                    ldm4(aL, sb + FA_QVL + offA);
                    uint32_t bH[2][4], bL[2][4];
                    #pragma unroll
                    for (int ni = 0; ni < 2; ni++) {
                        uint32_t offB = ((uint32_t)(wn + ni*16 + rr) * 72u + (uint32_t)(k16 + cc)) * 2u;
                        ldm4(bH[ni], sb + FA_RH + offB);
                        ldm4(bL[ni], sb + FA_RL + offB);
                    }
                    #pragma unroll
                    for (int ni = 0; ni < 2; ni++)
                        #pragma unroll
                        for (int hb = 0; hb < 2; hb++) {
                            int j = ni*2 + hb;
                            mma_bf16(bacc[j], aH, bH[ni][hb], bH[ni][hb+2]);
                            mma_bf16(bacc[j], aH, bL[ni][hb], bL[ni][hb+2]);
                            mma_bf16(bacc[j], aL, bH[ni][hb], bH[ni][hb+2]);
                        }
                }
                #pragma unroll
                for (int half = 0; half < 2; half++) {
                    int row = wm + qrow + half*8;
                    #pragma unroll
                    for (int j = 0; j < 4; j++) {
                        int col = hoff + wn + j*8 + kc0;
                        *(float2*)(sm + FA_BD + row*528 + col*4) =
                            make_float2(bacc[j][half*2], bacc[j][half*2+1]);
                    }
                }
            }
            if (pass == 0 && (kt != 0 || tnew > 15)) break;   // only one pass needed
            if (pass == 0) __syncthreads();                   // R buffer reusable
        }

        // ac MMAs
        float s[4][4];
        #pragma unroll
        for (int j = 0; j < 4; j++)
            #pragma unroll
            for (int q = 0; q < 4; q++) s[j][q] = 0.f;
        #pragma unroll
        for (int k16 = 0; k16 < 64; k16 += 16) {
            uint32_t aH[4], aL[4];
            uint32_t offA = ((uint32_t)(wm + rr) * 72u + (uint32_t)(k16 + cc)) * 2u;
            ldm4(aH, sb + FA_QUH + offA);
            ldm4(aL, sb + FA_QUL + offA);
            uint32_t bH[2][4], bL[2][4];
            #pragma unroll
            for (int ni = 0; ni < 2; ni++) {
                uint32_t offB = ((uint32_t)(wn + ni*16 + rr) * 72u + (uint32_t)(k16 + cc)) * 2u;
                ldm4(bH[ni], sb + FA_KH + offB);
                ldm4(bL[ni], sb + FA_KL + offB);
            }
            #pragma unroll
            for (int ni = 0; ni < 2; ni++)
                #pragma unroll
                for (int hb = 0; hb < 2; hb++) {
                    int j = ni*2 + hb;
                    mma_bf16(s[j], aH, bH[ni][hb], bH[ni][hb+2]);
                    mma_bf16(s[j], aH, bL[ni][hb], bL[ni][hb+2]);
                    mma_bf16(s[j], aL, bH[ni][hb], bH[ni][hb+2]);
                }
        }
        __syncthreads();   // BD visible; all K reads done

        bool diag = (kt == qt);
        int ringbase = (t0 & 1) * 64;
        float mt2[2], sc2[2], rs2[2];

        // phase 1: add bd, mask, per-warp row max -> smem
        #pragma unroll
        for (int half = 0; half < 2; half++) {
            int row = wm + qrow + half*8;
            float mt = -1e30f;
            #pragma unroll
            for (int j = 0; j < 4; j++) {
                #pragma unroll
                for (int c2 = 0; c2 < 2; c2++) {
                    int colk = wn + j*8 + kc0 + c2;
                    int jcol = colk - row + 63;
                    int phys = (ringbase + jcol) & 127;
                    float val = s[j][half*2 + c2] +
                        *(const float*)(sm + FA_BD + row*528 + phys*4);
                    if (diag && colk > row) val = -1e30f;
                    s[j][half*2 + c2] = val;
                    mt = fmaxf(mt, val);
                }
            }
            mt = fmaxf(mt, __shfl_xor_sync(0xFFFFFFFFu, mt, 1));
            mt = fmaxf(mt, __shfl_xor_sync(0xFFFFFFFFu, mt, 2));
            mt2[half] = mt;
            if ((lane & 3) == 0)
                *(float*)(sm + FA_RED + (wcol*64 + row)*4) = mt;
        }
        __syncthreads();

        // V loads into the K buffer (K reads complete); latency hidden by phase 2
        #pragma unroll
        for (int i = 0; i < 2; i++) {
            int slot = tid + 256*i;
            int row = slot >> 3, seg = slot & 7;
            size_t gv = ((size_t)bh*64 + row)*Sc + k0 + seg*8;
            *(uint4*)(sm + FA_KH + row*144 + seg*16) = *(const uint4*)(vth + gv);
            *(uint4*)(sm + FA_KL + row*144 + seg*16) = *(const uint4*)(vtl + gv);
        }

        // phase 2: combined max, exponentiate, partial sums -> smem (P stays in regs)
        #pragma unroll
        for (int half = 0; half < 2; half++) {
            int row = wm + qrow + half*8;
            float other = *(const float*)(sm + FA_RED + ((1-wcol)*64 + row)*4);
            float mnew = fmaxf(mrow[half], fmaxf(mt2[half], other));
            float scale = __expf(mrow[half] - mnew);
            sc2[half] = scale;
            float rs = 0.f;
            #pragma unroll
            for (int j = 0; j < 4; j++) {
                #pragma unroll
                for (int c2 = 0; c2 < 2; c2++) {
                    float p = __expf(s[j][half*2 + c2] - mnew);
                    s[j][half*2 + c2] = p;
                    rs += p;
                }
            }
            rs += __shfl_xor_sync(0xFFFFFFFFu, rs, 1);
            rs += __shfl_xor_sync(0xFFFFFFFFu, rs, 2);
            rs2[half] = rs;
            if ((lane & 3) == 0)
                *(float*)(sm + FA_RED + 512 + (wcol*64 + row)*4) = rs;
            mrow[half] = mnew;
            #pragma unroll
            for (int j = 0; j < 8; j++) {
                oacc[j][half*2 + 0] *= scale;
                oacc[j][half*2 + 1] *= scale;
            }
        }
        __syncthreads();   // row sums + V visible

        // phase 3: combine row sums
        #pragma unroll
        for (int half = 0; half < 2; half++) {
            int row = wm + qrow + half*8;
            float other = *(const float*)(sm + FA_RED + 512 + ((1-wcol)*64 + row)*4);
            lrow[half] = lrow[half] * sc2[half] + rs2[half] + other;
        }

        // PV MMAs: warp's 32-k slice (P from regs) x all 64 d-cols; V from K buffer
        #pragma unroll
        for (int kc = 0; kc < 2; kc++) {
            uint32_t aH[4], aL[4];
            {
                bf162 h0, l0;
                split2(s[2*kc][0],   s[2*kc][1],   h0, l0); aH[0] = *(uint32_t*)&h0; aL[0] = *(uint32_t*)&l0;
                split2(s[2*kc][2],   s[2*kc][3],   h0, l0); aH[1] = *(uint32_t*)&h0; aL[1] = *(uint32_t*)&l0;
                split2(s[2*kc+1][0], s[2*kc+1][1], h0, l0); aH[2] = *(uint32_t*)&h0; aL[2] = *(uint32_t*)&l0;
                split2(s[2*kc+1][2], s[2*kc+1][3], h0, l0); aH[3] = *(uint32_t*)&h0; aL[3] = *(uint32_t*)&l0;
            }
            #pragma unroll
            for (int ni = 0; ni < 4; ni++) {
                uint32_t bH[4], bL[4];
                uint32_t offB = ((uint32_t)(ni*16 + rr) * 72u + (uint32_t)(wn + kc*16 + cc)) * 2u;
                ldm4(bH, sb + FA_KH + offB);
                ldm4(bL, sb + FA_KL + offB);
                #pragma unroll
                for (int hb = 0; hb < 2; hb++) {
                    int j = ni*2 + hb;
                    mma_bf16(oacc[j], aH, bH[hb], bH[hb+2]);
                    mma_bf16(oacc[j], aH, bL[hb], bL[hb+2]);
                    mma_bf16(oacc[j], aL, bH[hb], bH[hb+2]);
                }
            }
        }
    }

    // epilogue: cross-warp partial sum (OS aliases BD; last BD read was pre-phase-2 sync)
    __syncthreads();
    if (wcol == 0) {
        #pragma unroll
        for (int half = 0; half < 2; half++) {
            int row = wm + qrow + half*8;
            #pragma unroll
            for (int j = 0; j < 8; j++) {
                *(float2*)(sm + FA_OS + row*272 + (j*8 + kc0)*4) =
                    make_float2(oacc[j][half*2], oacc[j][half*2+1]);
            }
        }
    }
    __syncthreads();
    if (wcol == 1) {
        #pragma unroll
        for (int half = 0; half < 2; half++) {
            int row = wm + qrow + half*8;
            int tok = b*Sc + q0 + row;
            float inv = 1.f / lrow[half];
            #pragma unroll
            for (int j = 0; j < 8; j++) {
                float2 o = *(float2*)(sm + FA_OS + row*272 + (j*8 + kc0)*4);
                float vx = (oacc[j][half*2 + 0] + o.x) * inv;
                float vy = (oacc[j][half*2 + 1] + o.y) * inv;
                int col = h*64 + j*8 + kc0;
                bf162 hh, ll;
                split2(vx, vy, hh, ll);
                *(bf162*)(ctxh + (size_t)tok*Dc + col) = hh;
                *(bf162*)(ctxl + (size_t)tok*Dc + col) = ll;
            }
        }
    }
}

// ---------------- residual + layernorm ----------------
// OBF: 0 = fp32 only, 1 = fp32 + bf16 hi/lo, 2 = bf16 hi/lo only
template<int OBF>
__global__ __launch_bounds__(256)
void rln_k(const float* __restrict__ x, const float* __restrict__ y,
           const float* __restrict__ g, const float* __restrict__ bta,
           float* __restrict__ out, bf16* __restrict__ oh, bf16* __restrict__ ol)
{
    int row = blockIdx.x;
    int tid = threadIdx.x;
    __shared__ float red[256];
    float v[4];
    float s = 0.f, ss = 0.f;
    #pragma unroll
    for (int l = 0; l < 4; l++) {
        size_t idx = (size_t)row*Dc + tid + l*256;
        float val = x[idx] + y[idx];
        v[l] = val; s += val; ss += val*val;
    }
    red[tid] = s; __syncthreads();
    for (int st = 128; st > 0; st >>= 1) { if (tid < st) red[tid] += red[tid+st]; __syncthreads(); }
    float mean = red[0] * (1.f/Dc); __syncthreads();
    red[tid] = ss; __syncthreads();
    for (int st = 128; st > 0; st >>= 1) { if (tid < st) red[tid] += red[tid+st]; __syncthreads(); }
    float var = red[0] * (1.f/Dc) - mean*mean;
    float inv = rsqrtf(var + 1e-5f);
    #pragma unroll
    for (int l = 0; l < 4; l++) {
        int c = tid + l*256;
        float o = (v[l] - mean) * inv * g[c] + bta[c];
        if (OBF != 2) out[(size_t)row*Dc + c] = o;
        if (OBF >= 1) {
            bf16 hh, ll; split1(o, hh, ll);
            oh[(size_t)row*Dc + c] = hh;
            ol[(size_t)row*Dc + c] = ll;
        }
    }
}

// ---------------- router ----------------
__global__ void zero_cnt(int* cnt) { if (threadIdx.x < NEc) cnt[threadIdx.x] = 0; }

__global__ __launch_bounds__(256)
void router_k(const float* __restrict__ h2, const float* __restrict__ Wg,
              float* __restrict__ gate, int* __restrict__ cnt, int* __restrict__ idxlist)
{
    int warp = (blockIdx.x * blockDim.x + threadIdx.x) >> 5;
    int lane = threadIdx.x & 31;
    if (warp >= Tc) return;
    const float* hrow = h2 + (size_t)warp * Dc;
    float logit[NEc];
    #pragma unroll
    for (int e = 0; e < NEc; e++) {
        float p = 0.f;
        for (int d = lane; d < Dc; d += 32) p += hrow[d] * Wg[d*NEc + e];
        #pragma unroll
        for (int off = 16; off > 0; off >>= 1) p += __shfl_xor_sync(0xFFFFFFFFu, p, off);
        logit[e] = p;
    }
    float m = logit[0]; int am = 0;
    #pragma unroll
    for (int e = 1; e < NEc; e++) if (logit[e] > m) { m = logit[e]; am = e; }
    float sum = 0.f;
    #pragma unroll
    for (int e = 0; e < NEc; e++) sum += expf(logit[e] - m);
    if (lane == 0) {
        gate[warp] = 1.f / sum;
        int pos = atomicAdd(&cnt[am], 1);
        idxlist[am*Tc + pos] = warp;
    }
}

// ---------------- launch ----------------
extern "C" void kernel_launch(void* const* d_in, const int* in_sizes, int n_in,
                              void* d_out, int out_size)
{
    const float* x    = (const float*)d_in[0];
    const float* Wqkv = (const float*)d_in[1];
    const float* Wo   = (const float*)d_in[2];
    const float* Wr   = (const float*)d_in[3];
    const float* u_b  = (const float*)d_in[4];
    const float* v_b  = (const float*)d_in[5];
    const float* ln1g = (const float*)d_in[6];
    const float* ln1b = (const float*)d_in[7];
    const float* Wff1 = (const float*)d_in[8];
    const float* bff1 = (const float*)d_in[9];
    const float* Wff2 = (const float*)d_in[10];
    const float* bff2 = (const float*)d_in[11];
    const float* ln2g = (const float*)d_in[12];
    const float* ln2b = (const float*)d_in[13];
    const float* Wg   = (const float*)d_in[14];
    const float* We1  = (const float*)d_in[15];
    const float* be1  = (const float*)d_in[16];
    const float* We2  = (const float*)d_in[17];
    const float* be2  = (const float*)d_in[18];
    const float* ln3g = (const float*)d_in[19];
    const float* ln3b = (const float*)d_in[20];
    const float* Wout = (const float*)d_in[21];
    float* out = (float*)d_out;

    static int inited = 0;
    if (!inited) {
        cudaFuncSetAttribute(tgemm<0,0>, cudaFuncAttributeMaxDynamicSharedMemorySize, TG_SMEM);
        cudaFuncSetAttribute(tgemm<1,0>, cudaFuncAttributeMaxDynamicSharedMemorySize, TG_SMEM);
        cudaFuncSetAttribute(tgemm<2,1>, cudaFuncAttributeMaxDynamicSharedMemorySize, TG_SMEM);
        cudaFuncSetAttribute(tgemm<3,0>, cudaFuncAttributeMaxDynamicSharedMemorySize, TG_SMEM);
        cudaFuncSetAttribute(fattn,      cudaFuncAttributeMaxDynamicSharedMemorySize, FA_SMEM);
        inited = 1;
    }

    float *qkv, *r, *ao, *ff, *h1, *h2, *moe, *gate;
    int *cnt, *idx;
    bf16 *whi, *wlo, *peh, *pel, *xh, *xl;
    bf16 *quh, *qul, *qvh, *qvl, *kh, *kl, *vth, *vtl, *rh, *rl;
    bf16 *ctxh, *ctxl, *h1h, *h1l, *h2h, *h2l, *h3h, *h3l, *ffhh, *ffhl;

    cudaGetSymbolAddress((void**)&qkv, g_qkv);
    cudaGetSymbolAddress((void**)&r,   g_r);
    cudaGetSymbolAddress((void**)&ao,  g_ao);
    cudaGetSymbolAddress((void**)&ff,  g_ff);
    cudaGetSymbolAddress((void**)&h1,  g_h1);
    cudaGetSymbolAddress((void**)&h2,  g_h2);
    cudaGetSymbolAddress((void**)&moe, g_moe);
    cudaGetSymbolAddress((void**)&gate,g_gate);
    cudaGetSymbolAddress((void**)&cnt, g_cnt);
    cudaGetSymbolAddress((void**)&idx, g_idx);
    cudaGetSymbolAddress((void**)&whi, g_whi);
    cudaGetSymbolAddress((void**)&wlo, g_wlo);
    cudaGetSymbolAddress((void**)&peh, g_peh);
    cudaGetSymbolAddress((void**)&pel, g_pel);
    cudaGetSymbolAddress((void**)&xh,  g_xh);
    cudaGetSymbolAddress((void**)&xl,  g_xl);
    cudaGetSymbolAddress((void**)&quh, g_quh);
    cudaGetSymbolAddress((void**)&qul, g_qul);
    cudaGetSymbolAddress((void**)&qvh, g_qvh);
    cudaGetSymbolAddress((void**)&qvl, g_qvl);
    cudaGetSymbolAddress((void**)&kh,  g_kh);
    cudaGetSymbolAddress((void**)&kl,  g_kl);
    cudaGetSymbolAddress((void**)&vth, g_vth);
    cudaGetSymbolAddress((void**)&vtl, g_vtl);
    cudaGetSymbolAddress((void**)&rh,  g_rh);
    cudaGetSymbolAddress((void**)&rl,  g_rl);
    cudaGetSymbolAddress((void**)&ctxh,g_ctxh);
    cudaGetSymbolAddress((void**)&ctxl,g_ctxl);
    cudaGetSymbolAddress((void**)&h1h, g_h1h);
    cudaGetSymbolAddress((void**)&h1l, g_h1l);
    cudaGetSymbolAddress((void**)&h2h, g_h2h);
    cudaGetSymbolAddress((void**)&h2l, g_h2l);
    cudaGetSymbolAddress((void**)&h3h, g_h3h);
    cudaGetSymbolAddress((void**)&h3l, g_h3l);
    cudaGetSymbolAddress((void**)&ffhh,g_ffhh);
    cudaGetSymbolAddress((void**)&ffhl,g_ffhl);

    // weight transpose + split
    wconv<<<dim3(3072/64, 1024/64), 256>>>(Wqkv, whi+OFF_QKV,  wlo+OFF_QKV,  1024, 3072);
    wconv<<<dim3(1024/64, 1024/64), 256>>>(Wr,   whi+OFF_WR,   wlo+OFF_WR,   1024, 1024);
    wconv<<<dim3(1024/64, 1024/64), 256>>>(Wo,   whi+OFF_WO,   wlo+OFF_WO,   1024, 1024);
    wconv<<<dim3(4096/64, 1024/64), 256>>>(Wff1, whi+OFF_FF1,  wlo+OFF_FF1,  1024, 4096);
    wconv<<<dim3(1024/64, 4096/64), 256>>>(Wff2, whi+OFF_FF2,  wlo+OFF_FF2,  4096, 1024);
    wconv<<<dim3(1024/64, 1024/64), 256>>>(Wout, whi+OFF_WOUT, wlo+OFF_WOUT, 1024, 1024);
    wconv<<<dim3(4096/64, 1024/64, NEc), 256>>>(We1, whi+OFF_WE1, wlo+OFF_WE1, 1024, 4096);
    wconv<<<dim3(1024/64, 4096/64, NEc), 256>>>(We2, whi+OFF_WE2, wlo+OFF_WE2, 4096, 1024);

    pe_kernel<<<Sc, 256>>>(peh, pel);
    econv<<<Tc, 256>>>(x, xh, xl);

    // projections
    tgemm<0,0><<<dim3(3072/128, Tc/128), 256, TG_SMEM>>>(xh, xl, whi+OFF_QKV, wlo+OFF_QKV,
        qkv, nullptr, nullptr, Tc, 3072, 1024, nullptr, nullptr, nullptr, nullptr, 0, 0);
    tgemm<0,0><<<dim3(1024/128, Sc/128), 256, TG_SMEM>>>(peh, pel, whi+OFF_WR, wlo+OFF_WR,
        r, nullptr, nullptr, Sc, 1024, 1024, nullptr, nullptr, nullptr, nullptr, 0, 0);

    // attention prep
    qprep<<<Tc, 256>>>(qkv, u_b, v_b, quh, qul, qvh, qvl, kh, kl);
    vtprep<<<dim3(Sc/32, 2, BHc), 256>>>(qkv, vth, vtl);
    rprep<<<Sc, 256>>>(r, rh, rl);

    // fused attention
    fattn<<<dim3(16, BHc), 256, FA_SMEM>>>(quh, qul, qvh, qvl, kh, kl, rh, rl,
                                           vth, vtl, ctxh, ctxl);
    tgemm<0,0><<<dim3(1024/128, Tc/128), 256, TG_SMEM>>>(ctxh, ctxl, whi+OFF_WO, wlo+OFF_WO,
        ao, nullptr, nullptr, Tc, 1024, 1024, nullptr, nullptr, nullptr, nullptr, 0, 0);
    rln_k<1><<<Tc, 256>>>(x, ao, ln1g, ln1b, h1, h1h, h1l);

    // FFN
    tgemm<2,1><<<dim3(4096/128, Tc/128), 256, TG_SMEM>>>(h1h, h1l, whi+OFF_FF1, wlo+OFF_FF1,
        nullptr, ffhh, ffhl, Tc, 4096, 1024, bff1, nullptr, nullptr, nullptr, 0, 0);
    tgemm<1,0><<<dim3(1024/128, Tc/128), 256, TG_SMEM>>>(ffhh, ffhl, whi+OFF_FF2, wlo+OFF_FF2,
        ff, nullptr, nullptr, Tc, 1024, 4096, bff2, nullptr, nullptr, nullptr, 0, 0);
    rln_k<1><<<Tc, 256>>>(h1, ff, ln2g, ln2b, h2, h2h, h2l);

    // MoE
    zero_cnt<<<1, 32>>>(cnt);
    router_k<<<Tc/8, 256>>>(h2, Wg, gate, cnt, idx);
    tgemm<2,1><<<dim3(4096/128, Tc/128, NEc), 256, TG_SMEM>>>(
        h2h, h2l, whi+OFF_WE1, wlo+OFF_WE1,
        nullptr, ffhh, ffhl, Tc, 4096, 1024, be1, nullptr, idx, cnt,
        (size_t)FFc*Dc, FFc);
    tgemm<3,0><<<dim3(1024/128, Tc/128, NEc), 256, TG_SMEM>>>(
        ffhh, ffhl, whi+OFF_WE2, wlo+OFF_WE2,
        moe, nullptr, nullptr, Tc, 1024, 4096, be2, gate, idx, cnt,
        (size_t)Dc*FFc, Dc);
    rln_k<2><<<Tc, 256>>>(h2, moe, ln3g, ln3b, nullptr, h3h, h3l);

    // output projection
    tgemm<0,0><<<dim3(1024/128, Tc/128), 256, TG_SMEM>>>(h3h, h3l, whi+OFF_WOUT, wlo+OFF_WOUT,
        out, nullptr, nullptr, Tc, 1024, 1024, nullptr, nullptr, nullptr, nullptr, 0, 0);
}